// round 7
// baseline (speedup 1.0000x reference)
#include <cuda_runtime.h>
#include <cuda_fp16.h>
#include <cstdint>
#include <math.h>

#define BB 4
#define TT 2048
#define CC 1024
#define NH 16
#define HD 64
#define M1 (BB*TT)          // 8192
#define N_QKV (3*CC)        // 3072

// ---------------------------------------------------------------------------
// Device-global scratch: pure fp16 operands.
// ---------------------------------------------------------------------------
__device__ __half g_xh[M1*CC];
__device__ __half g_wqh[N_QKV*CC];
__device__ __half g_wph[CC*CC];
__device__ __half g_qh[BB*NH*TT*HD];
__device__ __half g_kh[BB*NH*TT*HD];
__device__ __half g_vh[BB*NH*TT*HD];
__device__ __half g_ah[M1*CC];

// ---------------------------------------------------------------------------
// PTX helpers
// ---------------------------------------------------------------------------
__device__ __forceinline__ uint32_t smem_u32(const void* p) {
    uint32_t a;
    asm("{ .reg .u64 t; cvta.to.shared.u64 t, %1; cvt.u32.u64 %0, t; }"
        : "=r"(a) : "l"(p));
    return a;
}
__device__ __forceinline__ void cpasync16(uint32_t dst, const void* src) {
    asm volatile("cp.async.cg.shared.global [%0], [%1], 16;"
                 :: "r"(dst), "l"(src) : "memory");
}
#define CP_COMMIT() asm volatile("cp.async.commit_group;" ::: "memory")
#define CP_WAIT(N)  asm volatile("cp.async.wait_group %0;" :: "n"(N) : "memory")

__device__ __forceinline__ void ldsm4(uint32_t& r0, uint32_t& r1, uint32_t& r2,
                                      uint32_t& r3, uint32_t a) {
    asm volatile("ldmatrix.sync.aligned.m8n8.x4.shared.b16 {%0,%1,%2,%3},[%4];"
                 : "=r"(r0), "=r"(r1), "=r"(r2), "=r"(r3) : "r"(a));
}
__device__ __forceinline__ void ldsm4t(uint32_t& r0, uint32_t& r1, uint32_t& r2,
                                       uint32_t& r3, uint32_t a) {
    asm volatile("ldmatrix.sync.aligned.m8n8.x4.trans.shared.b16 {%0,%1,%2,%3},[%4];"
                 : "=r"(r0), "=r"(r1), "=r"(r2), "=r"(r3) : "r"(a));
}
__device__ __forceinline__ void mma16816(float* c, const uint32_t* a,
                                         uint32_t b0, uint32_t b1) {
    asm volatile("mma.sync.aligned.m16n8k16.row.col.f32.f16.f16.f32 "
                 "{%0,%1,%2,%3},{%4,%5,%6,%7},{%8,%9},{%0,%1,%2,%3};"
                 : "+f"(c[0]), "+f"(c[1]), "+f"(c[2]), "+f"(c[3])
                 : "r"(a[0]), "r"(a[1]), "r"(a[2]), "r"(a[3]), "r"(b0), "r"(b1));
}

__device__ __forceinline__ void hi_store(__half* dh, size_t off, float v0, float v1) {
    __half2 hp = __halves2half2(__float2half(v0), __float2half(v1));
    *(uint32_t*)(dh + off) = *(uint32_t*)&hp;
}
__device__ __forceinline__ uint32_t pack_h2(float v0, float v1) {
    __half2 hp = __halves2half2(__float2half(v0), __float2half(v1));
    return *(uint32_t*)&hp;
}

// ---------------------------------------------------------------------------
__global__ __launch_bounds__(256) void convert_x(const float* __restrict__ src)
{
    int i = blockIdx.x * 256 + threadIdx.x;
    float4 v = ((const float4*)src)[i];
    hi_store(g_xh, (size_t)i * 4,     v.x, v.y);
    hi_store(g_xh, (size_t)i * 4 + 2, v.z, v.w);
}

template<int W>
__global__ void transpose_w(const float* __restrict__ w)
{
    __half* th = (W == 0) ? g_wqh : g_wph;
    const int N = (W == 0) ? N_QKV : CC;
    __shared__ float ts[32][33];
    int n0 = blockIdx.x * 32, k0 = blockIdx.y * 32;
    int tx = threadIdx.x, ty = threadIdx.y;
    #pragma unroll
    for (int i = 0; i < 32; i += 8)
        ts[ty + i][tx] = w[(size_t)(k0 + ty + i) * N + n0 + tx];
    __syncthreads();
    #pragma unroll
    for (int i = 0; i < 32; i += 8)
        th[(size_t)(n0 + ty + i) * CC + k0 + tx] = __float2half(ts[tx][ty + i]);
}

// ---------------------------------------------------------------------------
// GEMM: C[128x128] = A[M,1024] @ B^T + bias. fp16, fp32 accum.
// 128 threads, 4 warps (2x2), 64x64 warp tile. 3-stage cp.async BK=32.
// ---------------------------------------------------------------------------
#define GST 20480
#define GSMEM (3*GST)

template<int EPI>
__global__ __launch_bounds__(128, 2) void mma_gemm(const float* __restrict__ bias,
                                                   float* __restrict__ outp)
{
    const __half* Ah = (EPI == 0) ? g_xh : g_ah;
    const __half* Bh = (EPI == 0) ? g_wqh : g_wph;

    extern __shared__ char smc[];
    const uint32_t smb = smem_u32(smc);
    const int t = threadIdx.x, wid = t >> 5, l = t & 31;
    const int wm = wid >> 1, wn = wid & 1;   // 2x2 warps, 64x64 each
    const int n0 = blockIdx.x * 128, m0 = blockIdx.y * 128;

    float acc[4][8][4];
    #pragma unroll
    for (int i = 0; i < 4; i++)
        #pragma unroll
        for (int j = 0; j < 8; j++)
            #pragma unroll
            for (int k = 0; k < 4; k++) acc[i][j][k] = 0.f;

    auto issue = [&](int s) {
        const int koff = s * 32;
        const uint32_t sb = smb + (s % 3) * GST;
        #pragma unroll
        for (int q = 0; q < 4; q++) {
            uint32_t so = (uint32_t)(t * 80 + q * 16);
            cpasync16(sb + so,         Ah + (size_t)(m0 + t) * CC + koff + q * 8);
            cpasync16(sb + 10240 + so, Bh + (size_t)(n0 + t) * CC + koff + q * 8);
        }
        CP_COMMIT();
    };

    issue(0);
    issue(1);
    for (int s = 0; s < 32; s++) {
        if (s < 30) CP_WAIT(1);
        else        CP_WAIT(0);
        __syncthreads();
        if (s + 2 < 32) issue(s + 2);
        const uint32_t sb = smb + (s % 3) * GST;
        #pragma unroll
        for (int ks = 0; ks < 2; ks++) {
            uint32_t ah[4][4];
            #pragma unroll
            for (int mt = 0; mt < 4; mt++) {
                uint32_t ad = sb + (uint32_t)((wm * 64 + mt * 16 + (l & 15)) * 80
                                              + ks * 32 + (l >> 4) * 16);
                ldsm4(ah[mt][0], ah[mt][1], ah[mt][2], ah[mt][3], ad);
            }
            uint32_t bh[8][2];
            #pragma unroll
            for (int j = 0; j < 4; j++) {
                uint32_t bd = sb + 10240
                    + (uint32_t)((wn * 64 + 16 * j + (l & 7) + ((l >> 4) & 1) * 8) * 80
                                 + ks * 32 + ((l >> 3) & 1) * 16);
                uint32_t r0, r1, r2, r3;
                ldsm4(r0, r1, r2, r3, bd);
                bh[2*j][0] = r0; bh[2*j][1] = r1; bh[2*j+1][0] = r2; bh[2*j+1][1] = r3;
            }
            #pragma unroll
            for (int mt = 0; mt < 4; mt++)
                #pragma unroll
                for (int nt = 0; nt < 8; nt++)
                    mma16816(acc[mt][nt], ah[mt], bh[nt][0], bh[nt][1]);
        }
    }

    #pragma unroll
    for (int mt = 0; mt < 4; mt++) {
        const int rA = m0 + wm * 64 + mt * 16 + (l >> 2);
        const int rB = rA + 8;
        #pragma unroll
        for (int nt = 0; nt < 8; nt++) {
            const int n = n0 + wn * 64 + nt * 8 + 2 * (l & 3);
            const float bi0 = bias[n], bi1 = bias[n + 1];
            float v0 = acc[mt][nt][0] + bi0, v1 = acc[mt][nt][1] + bi1;
            float v2 = acc[mt][nt][2] + bi0, v3 = acc[mt][nt][3] + bi1;
            if (EPI == 0) {
                const int which = n >> 10;
                const int h = (n & 1023) >> 6, d = n & 63;
                const int bA = rA >> 11, tA = rA & 2047;
                const int bB = rB >> 11, tB = rB & 2047;
                const size_t oA = (((size_t)(bA * NH + h)) * TT + tA) * HD + d;
                const size_t oB = (((size_t)(bB * NH + h)) * TT + tB) * HD + d;
                if (which == 0) {
                    hi_store(g_qh, oA, v0 * 0.125f, v1 * 0.125f);
                    hi_store(g_qh, oB, v2 * 0.125f, v3 * 0.125f);
                } else if (which == 1) {
                    hi_store(g_kh, oA, v0, v1);
                    hi_store(g_kh, oB, v2, v3);
                } else {
                    hi_store(g_vh, oA, v0, v1);
                    hi_store(g_vh, oB, v2, v3);
                }
            } else {
                *(float2*)&outp[(size_t)rA * CC + n] = make_float2(v0, v1);
                *(float2*)&outp[(size_t)rB * CC + n] = make_float2(v2, v3);
            }
        }
    }
}

// ---------------------------------------------------------------------------
// Flash attention, fp16. 128 thr / 4 warps; warp owns 32 q-rows (2 m-tiles);
// q-tile = 128 rows; 64-col KV tiles, 3 stages.
// smem: Qh@0 (18432) | 3 KV stages @18432 + stg*18432 (Kh, Vh@+9216)
// ---------------------------------------------------------------------------
#define FKV_OFF 18432
#define FKV_ST 18432
#define FLASH_SMEM (FKV_OFF + 3*FKV_ST)   // 73728

__global__ __launch_bounds__(128, 2) void flash_mma()
{
    extern __shared__ char smc[];
    const uint32_t smb = smem_u32(smc);
    const int t = threadIdx.x, w = t >> 5, l = t & 31;
    const int qt = (int)gridDim.x - 1 - (int)blockIdx.x;   // heavy tiles first
    const int h = blockIdx.y, b = blockIdx.z;
    const size_t hoff = ((size_t)(b * NH + h)) * TT * HD;
    const int q0 = qt * 128;
    const int nk = 2 * qt + 2;

    auto kvload = [&](int kt) {
        const uint32_t sb = smb + FKV_OFF + (kt % 3) * FKV_ST;
        const int k0 = kt * 64;
        #pragma unroll
        for (int i = 0; i < 4; i++) {
            int c = t + i * 128, row = c >> 3, q = c & 7;
            uint32_t so = (uint32_t)(row * 144 + q * 16);
            size_t g = hoff + (size_t)(k0 + row) * HD + q * 8;
            cpasync16(sb + so,        g_kh + g);
            cpasync16(sb + 9216 + so, g_vh + g);
        }
        CP_COMMIT();
    };

    // Q: 128 rows x 8 chunks = 1024; 128 thr x 8
    #pragma unroll
    for (int i = 0; i < 8; i++) {
        int c = t + i * 128, row = c >> 3, q = c & 7;
        uint32_t so = (uint32_t)(row * 144 + q * 16);
        cpasync16(smb + so, g_qh + hoff + (size_t)(q0 + row) * HD + q * 8);
    }
    kvload(0);
    kvload(1);

    float mr[2][2], lr[2][2];
    #pragma unroll
    for (int mt = 0; mt < 2; mt++) {
        mr[mt][0] = -1e30f; mr[mt][1] = -1e30f;
        lr[mt][0] = 0.f;    lr[mt][1] = 0.f;
    }
    float o[2][8][4];
    #pragma unroll
    for (int mt = 0; mt < 2; mt++)
        #pragma unroll
        for (int j = 0; j < 8; j++)
            #pragma unroll
            for (int k = 0; k < 4; k++) o[mt][j][k] = 0.f;

    uint32_t qh[2][4][4];

    for (int kt = 0; kt < nk; kt++) {
        if (kt < nk - 1) CP_WAIT(1);
        else             CP_WAIT(0);
        __syncthreads();
        if (kt + 2 < nk) kvload(kt + 2);
        if (kt == 0) {
            #pragma unroll
            for (int mt = 0; mt < 2; mt++)
                #pragma unroll
                for (int ks = 0; ks < 4; ks++) {
                    uint32_t ad = smb + (uint32_t)((w * 32 + mt * 16 + (l & 15)) * 144
                                                   + ks * 32 + (l >> 4) * 16);
                    ldsm4(qh[mt][ks][0], qh[mt][ks][1], qh[mt][ks][2], qh[mt][ks][3], ad);
                }
        }
        const uint32_t sb = smb + FKV_OFF + (kt % 3) * FKV_ST;

        // S = Q K^T
        float s[2][8][4];
        #pragma unroll
        for (int mt = 0; mt < 2; mt++)
            #pragma unroll
            for (int j = 0; j < 8; j++)
                #pragma unroll
                for (int k = 0; k < 4; k++) s[mt][j][k] = 0.f;
        #pragma unroll
        for (int ks = 0; ks < 4; ks++) {
            #pragma unroll
            for (int j = 0; j < 4; j++) {
                uint32_t kd = sb + (uint32_t)((16 * j + (l & 7) + ((l >> 4) & 1) * 8) * 144
                                              + ks * 32 + ((l >> 3) & 1) * 16);
                uint32_t r0, r1, r2, r3;
                ldsm4(r0, r1, r2, r3, kd);
                #pragma unroll
                for (int mt = 0; mt < 2; mt++) {
                    mma16816(s[mt][2*j],   qh[mt][ks], r0, r1);
                    mma16816(s[mt][2*j+1], qh[mt][ks], r2, r3);
                }
            }
        }

        if (kt >= 2 * qt) {
            const int cb = 2 * (l & 3);
            #pragma unroll
            for (int mt = 0; mt < 2; mt++) {
                const int rA = q0 + w * 32 + mt * 16 + (l >> 2), rB = rA + 8;
                #pragma unroll
                for (int j = 0; j < 8; j++) {
                    int cg = kt * 64 + 8 * j + cb;
                    if (cg     > rA) s[mt][j][0] = -1e30f;
                    if (cg + 1 > rA) s[mt][j][1] = -1e30f;
                    if (cg     > rB) s[mt][j][2] = -1e30f;
                    if (cg + 1 > rB) s[mt][j][3] = -1e30f;
                }
            }
        }

        // online softmax (per m-tile)
        float alpha[2][2];
        #pragma unroll
        for (int mt = 0; mt < 2; mt++) {
            float mxA = -1e30f, mxB = -1e30f;
            #pragma unroll
            for (int j = 0; j < 8; j++) {
                mxA = fmaxf(mxA, fmaxf(s[mt][j][0], s[mt][j][1]));
                mxB = fmaxf(mxB, fmaxf(s[mt][j][2], s[mt][j][3]));
            }
            mxA = fmaxf(mxA, __shfl_xor_sync(0xffffffffu, mxA, 1));
            mxA = fmaxf(mxA, __shfl_xor_sync(0xffffffffu, mxA, 2));
            mxB = fmaxf(mxB, __shfl_xor_sync(0xffffffffu, mxB, 1));
            mxB = fmaxf(mxB, __shfl_xor_sync(0xffffffffu, mxB, 2));
            const float nmA = fmaxf(mr[mt][0], mxA), nmB = fmaxf(mr[mt][1], mxB);
            alpha[mt][0] = __expf(mr[mt][0] - nmA);
            alpha[mt][1] = __expf(mr[mt][1] - nmB);
            mr[mt][0] = nmA; mr[mt][1] = nmB;
            float suA = 0.f, suB = 0.f;
            #pragma unroll
            for (int j = 0; j < 8; j++) {
                s[mt][j][0] = __expf(s[mt][j][0] - nmA);
                s[mt][j][1] = __expf(s[mt][j][1] - nmA);
                s[mt][j][2] = __expf(s[mt][j][2] - nmB);
                s[mt][j][3] = __expf(s[mt][j][3] - nmB);
                suA += s[mt][j][0] + s[mt][j][1];
                suB += s[mt][j][2] + s[mt][j][3];
            }
            suA += __shfl_xor_sync(0xffffffffu, suA, 1);
            suA += __shfl_xor_sync(0xffffffffu, suA, 2);
            suB += __shfl_xor_sync(0xffffffffu, suB, 1);
            suB += __shfl_xor_sync(0xffffffffu, suB, 2);
            lr[mt][0] = lr[mt][0] * alpha[mt][0] + suA;
            lr[mt][1] = lr[mt][1] * alpha[mt][1] + suB;
            #pragma unroll
            for (int j = 0; j < 8; j++) {
                o[mt][j][0] *= alpha[mt][0]; o[mt][j][1] *= alpha[mt][0];
                o[mt][j][2] *= alpha[mt][1]; o[mt][j][3] *= alpha[mt][1];
            }
        }

        // O += P V  (V via ldmatrix.trans)
        #pragma unroll
        for (int ks = 0; ks < 4; ks++) {
            uint32_t pa[2][4];
            #pragma unroll
            for (int mt = 0; mt < 2; mt++) {
                pa[mt][0] = pack_h2(s[mt][2*ks][0],   s[mt][2*ks][1]);
                pa[mt][1] = pack_h2(s[mt][2*ks][2],   s[mt][2*ks][3]);
                pa[mt][2] = pack_h2(s[mt][2*ks+1][0], s[mt][2*ks+1][1]);
                pa[mt][3] = pack_h2(s[mt][2*ks+1][2], s[mt][2*ks+1][3]);
            }
            #pragma unroll
            for (int j = 0; j < 4; j++) {
                uint32_t vd = sb + 9216
                    + (uint32_t)((ks * 16 + (l & 7) + ((l >> 3) & 1) * 8) * 144
                                 + 32 * j + ((l >> 4) & 1) * 16);
                uint32_t r0, r1, r2, r3;
                ldsm4t(r0, r1, r2, r3, vd);
                #pragma unroll
                for (int mt = 0; mt < 2; mt++) {
                    mma16816(o[mt][2*j],   pa[mt], r0, r1);
                    mma16816(o[mt][2*j+1], pa[mt], r2, r3);
                }
            }
        }
    }

    #pragma unroll
    for (int mt = 0; mt < 2; mt++) {
        const float iA = 1.f / lr[mt][0], iB = 1.f / lr[mt][1];
        const int rA = q0 + w * 32 + mt * 16 + (l >> 2), rB = rA + 8;
        const size_t baseA = ((size_t)(b * TT + rA)) * CC + h * HD;
        const size_t baseB = ((size_t)(b * TT + rB)) * CC + h * HD;
        #pragma unroll
        for (int j = 0; j < 8; j++) {
            const int d = 8 * j + 2 * (l & 3);
            hi_store(g_ah, baseA + d, o[mt][j][0] * iA, o[mt][j][1] * iA);
            hi_store(g_ah, baseB + d, o[mt][j][2] * iB, o[mt][j][3] * iB);
        }
    }
}

// ---------------------------------------------------------------------------
extern "C" void kernel_launch(void* const* d_in, const int* in_sizes, int n_in,
                              void* d_out, int out_size)
{
    const float* x      = (const float*)d_in[0];
    const float* w_attn = (const float*)d_in[1];
    const float* b_attn = (const float*)d_in[2];
    const float* w_proj = (const float*)d_in[3];
    const float* b_proj = (const float*)d_in[4];
    float* out = (float*)d_out;

    cudaFuncSetAttribute(mma_gemm<0>, cudaFuncAttributeMaxDynamicSharedMemorySize, GSMEM);
    cudaFuncSetAttribute(mma_gemm<1>, cudaFuncAttributeMaxDynamicSharedMemorySize, GSMEM);
    cudaFuncSetAttribute(flash_mma, cudaFuncAttributeMaxDynamicSharedMemorySize, FLASH_SMEM);

    convert_x<<<M1 * CC / 1024, 256>>>(x);
    transpose_w<0><<<dim3(N_QKV / 32, CC / 32), dim3(32, 8)>>>(w_attn);
    transpose_w<1><<<dim3(CC / 32, CC / 32), dim3(32, 8)>>>(w_proj);

    mma_gemm<0><<<dim3(N_QKV / 128, M1 / 128), 128, GSMEM>>>(b_attn, nullptr);
    flash_mma<<<dim3(TT / 128, NH, BB), 128, FLASH_SMEM>>>();
    mma_gemm<1><<<dim3(CC / 128, M1 / 128), 128, GSMEM>>>(b_proj, out);
}

// round 8
// speedup vs baseline: 1.3448x; 1.3448x over previous
#include <cuda_runtime.h>
#include <cuda_fp16.h>
#include <cstdint>
#include <math.h>

#define BB 4
#define TT 2048
#define CC 1024
#define NH 16
#define HD 64
#define M1 (BB*TT)          // 8192
#define N_QKV (3*CC)        // 3072

// ---------------------------------------------------------------------------
// Device-global scratch: pure fp16 operands.
// ---------------------------------------------------------------------------
__device__ __half g_xh[M1*CC];
__device__ __half g_wqh[N_QKV*CC];
__device__ __half g_wph[CC*CC];
__device__ __half g_qh[BB*NH*TT*HD];
__device__ __half g_kh[BB*NH*TT*HD];
__device__ __half g_vh[BB*NH*TT*HD];
__device__ __half g_ah[M1*CC];

// ---------------------------------------------------------------------------
// PTX helpers
// ---------------------------------------------------------------------------
__device__ __forceinline__ uint32_t smem_u32(const void* p) {
    uint32_t a;
    asm("{ .reg .u64 t; cvta.to.shared.u64 t, %1; cvt.u32.u64 %0, t; }"
        : "=r"(a) : "l"(p));
    return a;
}
__device__ __forceinline__ void cpasync16(uint32_t dst, const void* src) {
    asm volatile("cp.async.cg.shared.global [%0], [%1], 16;"
                 :: "r"(dst), "l"(src) : "memory");
}
#define CP_COMMIT() asm volatile("cp.async.commit_group;" ::: "memory")
#define CP_WAIT(N)  asm volatile("cp.async.wait_group %0;" :: "n"(N) : "memory")

__device__ __forceinline__ void ldsm4(uint32_t& r0, uint32_t& r1, uint32_t& r2,
                                      uint32_t& r3, uint32_t a) {
    asm volatile("ldmatrix.sync.aligned.m8n8.x4.shared.b16 {%0,%1,%2,%3},[%4];"
                 : "=r"(r0), "=r"(r1), "=r"(r2), "=r"(r3) : "r"(a));
}
__device__ __forceinline__ void ldsm4t(uint32_t& r0, uint32_t& r1, uint32_t& r2,
                                       uint32_t& r3, uint32_t a) {
    asm volatile("ldmatrix.sync.aligned.m8n8.x4.trans.shared.b16 {%0,%1,%2,%3},[%4];"
                 : "=r"(r0), "=r"(r1), "=r"(r2), "=r"(r3) : "r"(a));
}
__device__ __forceinline__ void mma16816(float* c, const uint32_t* a,
                                         uint32_t b0, uint32_t b1) {
    asm volatile("mma.sync.aligned.m16n8k16.row.col.f32.f16.f16.f32 "
                 "{%0,%1,%2,%3},{%4,%5,%6,%7},{%8,%9},{%0,%1,%2,%3};"
                 : "+f"(c[0]), "+f"(c[1]), "+f"(c[2]), "+f"(c[3])
                 : "r"(a[0]), "r"(a[1]), "r"(a[2]), "r"(a[3]), "r"(b0), "r"(b1));
}

__device__ __forceinline__ void hi_store(__half* dh, size_t off, float v0, float v1) {
    __half2 hp = __halves2half2(__float2half(v0), __float2half(v1));
    *(uint32_t*)(dh + off) = *(uint32_t*)&hp;
}
__device__ __forceinline__ uint32_t pack_h2(float v0, float v1) {
    __half2 hp = __halves2half2(__float2half(v0), __float2half(v1));
    return *(uint32_t*)&hp;
}

// ---------------------------------------------------------------------------
__global__ __launch_bounds__(256) void convert_x(const float* __restrict__ src)
{
    int i = blockIdx.x * 256 + threadIdx.x;
    float4 v = ((const float4*)src)[i];
    hi_store(g_xh, (size_t)i * 4,     v.x, v.y);
    hi_store(g_xh, (size_t)i * 4 + 2, v.z, v.w);
}

template<int W>
__global__ void transpose_w(const float* __restrict__ w)
{
    __half* th = (W == 0) ? g_wqh : g_wph;
    const int N = (W == 0) ? N_QKV : CC;
    __shared__ float ts[32][33];
    int n0 = blockIdx.x * 32, k0 = blockIdx.y * 32;
    int tx = threadIdx.x, ty = threadIdx.y;
    #pragma unroll
    for (int i = 0; i < 32; i += 8)
        ts[ty + i][tx] = w[(size_t)(k0 + ty + i) * N + n0 + tx];
    __syncthreads();
    #pragma unroll
    for (int i = 0; i < 32; i += 8)
        th[(size_t)(n0 + ty + i) * CC + k0 + tx] = __float2half(ts[tx][ty + i]);
}

// ---------------------------------------------------------------------------
// GEMM: C[128x128] = A[M,1024] @ B^T + bias. fp16, fp32 accum.
// 256 threads, 8 warps (2x4), 64x32 warp tile. BK=64, 3-stage cp.async,
// ONE __syncthreads per K-iter (16 iters).
// stage: A 128x144B + B 128x144B = 36864 B
// ---------------------------------------------------------------------------
#define GST 36864
#define GSMEM (3*GST)   // 110592; x2 CTA = 221184 <= 227KB

template<int EPI>
__global__ __launch_bounds__(256, 2) void mma_gemm(const float* __restrict__ bias,
                                                   float* __restrict__ outp)
{
    const __half* Ah = (EPI == 0) ? g_xh : g_ah;
    const __half* Bh = (EPI == 0) ? g_wqh : g_wph;

    extern __shared__ char smc[];
    const uint32_t smb = smem_u32(smc);
    const int t = threadIdx.x, wid = t >> 5, l = t & 31;
    const int wm = wid >> 2, wn = wid & 3;   // 2x4 warps, 64x32 each
    const int n0 = blockIdx.x * 128, m0 = blockIdx.y * 128;

    float acc[4][4][4];
    #pragma unroll
    for (int i = 0; i < 4; i++)
        #pragma unroll
        for (int j = 0; j < 4; j++)
            #pragma unroll
            for (int k = 0; k < 4; k++) acc[i][j][k] = 0.f;

    auto issue = [&](int s) {
        const int koff = s * 64;
        const uint32_t sb = smb + (s % 3) * GST;
        #pragma unroll
        for (int i = 0; i < 4; i++) {
            int c = t + i * 256;            // 0..1023
            int row = c >> 3, q = c & 7;
            uint32_t so = (uint32_t)(row * 144 + q * 16);
            cpasync16(sb + so,         Ah + (size_t)(m0 + row) * CC + koff + q * 8);
            cpasync16(sb + 18432 + so, Bh + (size_t)(n0 + row) * CC + koff + q * 8);
        }
        CP_COMMIT();
    };

    issue(0);
    issue(1);
    for (int s = 0; s < 16; s++) {
        if (s < 14) CP_WAIT(1);
        else        CP_WAIT(0);
        __syncthreads();
        if (s + 2 < 16) issue(s + 2);
        const uint32_t sb = smb + (s % 3) * GST;
        #pragma unroll
        for (int ks = 0; ks < 4; ks++) {
            uint32_t ah[4][4];
            #pragma unroll
            for (int mt = 0; mt < 4; mt++) {
                uint32_t ad = sb + (uint32_t)((wm * 64 + mt * 16 + (l & 15)) * 144
                                              + ks * 32 + (l >> 4) * 16);
                ldsm4(ah[mt][0], ah[mt][1], ah[mt][2], ah[mt][3], ad);
            }
            uint32_t bh[4][2];
            #pragma unroll
            for (int j = 0; j < 2; j++) {
                uint32_t bd = sb + 18432
                    + (uint32_t)((wn * 32 + 16 * j + (l & 7) + ((l >> 4) & 1) * 8) * 144
                                 + ks * 32 + ((l >> 3) & 1) * 16);
                uint32_t r0, r1, r2, r3;
                ldsm4(r0, r1, r2, r3, bd);
                bh[2*j][0] = r0; bh[2*j][1] = r1; bh[2*j+1][0] = r2; bh[2*j+1][1] = r3;
            }
            #pragma unroll
            for (int mt = 0; mt < 4; mt++)
                #pragma unroll
                for (int nt = 0; nt < 4; nt++)
                    mma16816(acc[mt][nt], ah[mt], bh[nt][0], bh[nt][1]);
        }
    }

    #pragma unroll
    for (int mt = 0; mt < 4; mt++) {
        const int rA = m0 + wm * 64 + mt * 16 + (l >> 2);
        const int rB = rA + 8;
        #pragma unroll
        for (int nt = 0; nt < 4; nt++) {
            const int n = n0 + wn * 32 + nt * 8 + 2 * (l & 3);
            const float bi0 = bias[n], bi1 = bias[n + 1];
            float v0 = acc[mt][nt][0] + bi0, v1 = acc[mt][nt][1] + bi1;
            float v2 = acc[mt][nt][2] + bi0, v3 = acc[mt][nt][3] + bi1;
            if (EPI == 0) {
                const int which = n >> 10;
                const int h = (n & 1023) >> 6, d = n & 63;
                const int bA = rA >> 11, tA = rA & 2047;
                const int bB = rB >> 11, tB = rB & 2047;
                const size_t oA = (((size_t)(bA * NH + h)) * TT + tA) * HD + d;
                const size_t oB = (((size_t)(bB * NH + h)) * TT + tB) * HD + d;
                if (which == 0) {
                    hi_store(g_qh, oA, v0 * 0.125f, v1 * 0.125f);
                    hi_store(g_qh, oB, v2 * 0.125f, v3 * 0.125f);
                } else if (which == 1) {
                    hi_store(g_kh, oA, v0, v1);
                    hi_store(g_kh, oB, v2, v3);
                } else {
                    hi_store(g_vh, oA, v0, v1);
                    hi_store(g_vh, oB, v2, v3);
                }
            } else {
                *(float2*)&outp[(size_t)rA * CC + n] = make_float2(v0, v1);
                *(float2*)&outp[(size_t)rB * CC + n] = make_float2(v2, v3);
            }
        }
    }
}

// ---------------------------------------------------------------------------
// Flash attention, fp16 (R6 config: 256 thr / 8 warps, 128-row q tile,
// 64-col KV, 3 stages, one sync per KV tile).
// smem: Qh@0 (18432) | 3 KV stages @18432 + stg*18432 (Kh, Vh@+9216)
// ---------------------------------------------------------------------------
#define FKV_OFF 18432
#define FKV_ST 18432
#define FLASH_SMEM (FKV_OFF + 3*FKV_ST)   // 73728

__global__ __launch_bounds__(256, 2) void flash_mma()
{
    extern __shared__ char smc[];
    const uint32_t smb = smem_u32(smc);
    const int t = threadIdx.x, w = t >> 5, l = t & 31;
    const int qt = (int)gridDim.x - 1 - (int)blockIdx.x;   // heavy tiles first
    const int h = blockIdx.y, b = blockIdx.z;
    const size_t hoff = ((size_t)(b * NH + h)) * TT * HD;
    const int q0 = qt * 128;
    const int nk = 2 * qt + 2;

    auto kvload = [&](int kt) {
        const uint32_t sb = smb + FKV_OFF + (kt % 3) * FKV_ST;
        const int k0 = kt * 64;
        #pragma unroll
        for (int i = 0; i < 2; i++) {
            int c = t + i * 256, row = c >> 3, q = c & 7;
            uint32_t so = (uint32_t)(row * 144 + q * 16);
            size_t g = hoff + (size_t)(k0 + row) * HD + q * 8;
            cpasync16(sb + so,        g_kh + g);
            cpasync16(sb + 9216 + so, g_vh + g);
        }
        CP_COMMIT();
    };

    // Q: 128 rows x 8 chunks = 1024; 256 thr x 4
    #pragma unroll
    for (int i = 0; i < 4; i++) {
        int c = t + i * 256, row = c >> 3, q = c & 7;
        uint32_t so = (uint32_t)(row * 144 + q * 16);
        cpasync16(smb + so, g_qh + hoff + (size_t)(q0 + row) * HD + q * 8);
    }
    kvload(0);
    kvload(1);

    float mA = -1e30f, mB = -1e30f, lA = 0.f, lB = 0.f;
    float o[8][4];
    #pragma unroll
    for (int j = 0; j < 8; j++)
        #pragma unroll
        for (int k = 0; k < 4; k++) o[j][k] = 0.f;

    uint32_t qh[4][4];

    for (int kt = 0; kt < nk; kt++) {
        if (kt < nk - 1) CP_WAIT(1);
        else             CP_WAIT(0);
        __syncthreads();
        if (kt + 2 < nk) kvload(kt + 2);
        if (kt == 0) {
            #pragma unroll
            for (int ks = 0; ks < 4; ks++) {
                uint32_t ad = smb + (uint32_t)((w * 16 + (l & 15)) * 144
                                               + ks * 32 + (l >> 4) * 16);
                ldsm4(qh[ks][0], qh[ks][1], qh[ks][2], qh[ks][3], ad);
            }
        }
        const uint32_t sb = smb + FKV_OFF + (kt % 3) * FKV_ST;

        // S = Q K^T
        float s[8][4];
        #pragma unroll
        for (int j = 0; j < 8; j++)
            #pragma unroll
            for (int k = 0; k < 4; k++) s[j][k] = 0.f;
        #pragma unroll
        for (int ks = 0; ks < 4; ks++) {
            #pragma unroll
            for (int j = 0; j < 4; j++) {
                uint32_t kd = sb + (uint32_t)((16 * j + (l & 7) + ((l >> 4) & 1) * 8) * 144
                                              + ks * 32 + ((l >> 3) & 1) * 16);
                uint32_t r0, r1, r2, r3;
                ldsm4(r0, r1, r2, r3, kd);
                mma16816(s[2*j],   qh[ks], r0, r1);
                mma16816(s[2*j+1], qh[ks], r2, r3);
            }
        }

        const int rA = q0 + w * 16 + (l >> 2), rB = rA + 8;
        if (kt >= 2 * qt) {
            const int cb = 2 * (l & 3);
            #pragma unroll
            for (int j = 0; j < 8; j++) {
                int cg = kt * 64 + 8 * j + cb;
                if (cg     > rA) s[j][0] = -1e30f;
                if (cg + 1 > rA) s[j][1] = -1e30f;
                if (cg     > rB) s[j][2] = -1e30f;
                if (cg + 1 > rB) s[j][3] = -1e30f;
            }
        }

        // online softmax
        float mxA = -1e30f, mxB = -1e30f;
        #pragma unroll
        for (int j = 0; j < 8; j++) {
            mxA = fmaxf(mxA, fmaxf(s[j][0], s[j][1]));
            mxB = fmaxf(mxB, fmaxf(s[j][2], s[j][3]));
        }
        mxA = fmaxf(mxA, __shfl_xor_sync(0xffffffffu, mxA, 1));
        mxA = fmaxf(mxA, __shfl_xor_sync(0xffffffffu, mxA, 2));
        mxB = fmaxf(mxB, __shfl_xor_sync(0xffffffffu, mxB, 1));
        mxB = fmaxf(mxB, __shfl_xor_sync(0xffffffffu, mxB, 2));
        const float nmA = fmaxf(mA, mxA), nmB = fmaxf(mB, mxB);
        const float aA = __expf(mA - nmA), aB = __expf(mB - nmB);
        mA = nmA; mB = nmB;
        float suA = 0.f, suB = 0.f;
        #pragma unroll
        for (int j = 0; j < 8; j++) {
            s[j][0] = __expf(s[j][0] - mA);
            s[j][1] = __expf(s[j][1] - mA);
            s[j][2] = __expf(s[j][2] - mB);
            s[j][3] = __expf(s[j][3] - mB);
            suA += s[j][0] + s[j][1];
            suB += s[j][2] + s[j][3];
        }
        suA += __shfl_xor_sync(0xffffffffu, suA, 1);
        suA += __shfl_xor_sync(0xffffffffu, suA, 2);
        suB += __shfl_xor_sync(0xffffffffu, suB, 1);
        suB += __shfl_xor_sync(0xffffffffu, suB, 2);
        lA = lA * aA + suA;
        lB = lB * aB + suB;
        #pragma unroll
        for (int j = 0; j < 8; j++) {
            o[j][0] *= aA; o[j][1] *= aA; o[j][2] *= aB; o[j][3] *= aB;
        }

        // O += P V (V via ldmatrix.trans)
        #pragma unroll
        for (int ks = 0; ks < 4; ks++) {
            uint32_t pa[4];
            pa[0] = pack_h2(s[2*ks][0],   s[2*ks][1]);
            pa[1] = pack_h2(s[2*ks][2],   s[2*ks][3]);
            pa[2] = pack_h2(s[2*ks+1][0], s[2*ks+1][1]);
            pa[3] = pack_h2(s[2*ks+1][2], s[2*ks+1][3]);
            #pragma unroll
            for (int j = 0; j < 4; j++) {
                uint32_t vd = sb + 9216
                    + (uint32_t)((ks * 16 + (l & 7) + ((l >> 3) & 1) * 8) * 144
                                 + 32 * j + ((l >> 4) & 1) * 16);
                uint32_t r0, r1, r2, r3;
                ldsm4t(r0, r1, r2, r3, vd);
                mma16816(o[2*j],   pa, r0, r1);
                mma16816(o[2*j+1], pa, r2, r3);
            }
        }
    }

    const float iA = 1.f / lA, iB = 1.f / lB;
    const int rA = q0 + w * 16 + (l >> 2), rB = rA + 8;
    const size_t baseA = ((size_t)(b * TT + rA)) * CC + h * HD;
    const size_t baseB = ((size_t)(b * TT + rB)) * CC + h * HD;
    #pragma unroll
    for (int j = 0; j < 8; j++) {
        const int d = 8 * j + 2 * (l & 3);
        hi_store(g_ah, baseA + d, o[j][0] * iA, o[j][1] * iA);
        hi_store(g_ah, baseB + d, o[j][2] * iB, o[j][3] * iB);
    }
}

// ---------------------------------------------------------------------------
extern "C" void kernel_launch(void* const* d_in, const int* in_sizes, int n_in,
                              void* d_out, int out_size)
{
    const float* x      = (const float*)d_in[0];
    const float* w_attn = (const float*)d_in[1];
    const float* b_attn = (const float*)d_in[2];
    const float* w_proj = (const float*)d_in[3];
    const float* b_proj = (const float*)d_in[4];
    float* out = (float*)d_out;

    cudaFuncSetAttribute(mma_gemm<0>, cudaFuncAttributeMaxDynamicSharedMemorySize, GSMEM);
    cudaFuncSetAttribute(mma_gemm<1>, cudaFuncAttributeMaxDynamicSharedMemorySize, GSMEM);
    cudaFuncSetAttribute(flash_mma, cudaFuncAttributeMaxDynamicSharedMemorySize, FLASH_SMEM);

    convert_x<<<M1 * CC / 1024, 256>>>(x);
    transpose_w<0><<<dim3(N_QKV / 32, CC / 32), dim3(32, 8)>>>(w_attn);
    transpose_w<1><<<dim3(CC / 32, CC / 32), dim3(32, 8)>>>(w_proj);

    mma_gemm<0><<<dim3(N_QKV / 128, M1 / 128), 256, GSMEM>>>(b_attn, nullptr);
    flash_mma<<<dim3(TT / 128, NH, BB), 256, FLASH_SMEM>>>();
    mma_gemm<1><<<dim3(CC / 128, M1 / 128), 256, GSMEM>>>(b_proj, out);
}

// round 9
// speedup vs baseline: 1.3918x; 1.0349x over previous
#include <cuda_runtime.h>
#include <cuda_fp16.h>
#include <cstdint>
#include <math.h>

#define BB 4
#define TT 2048
#define CC 1024
#define NH 16
#define HD 64
#define M1 (BB*TT)          // 8192
#define N_QKV (3*CC)        // 3072

// q pre-scale: 1/sqrt(64) * log2(e)  -> softmax computed base-2
#define QSCALE 0.180336880111120436f

// ---------------------------------------------------------------------------
// Device-global scratch: pure fp16 operands.
// ---------------------------------------------------------------------------
__device__ __half g_xh[M1*CC];
__device__ __half g_wqh[N_QKV*CC];
__device__ __half g_wph[CC*CC];
__device__ __half g_qh[BB*NH*TT*HD];
__device__ __half g_kh[BB*NH*TT*HD];
__device__ __half g_vh[BB*NH*TT*HD];
__device__ __half g_ah[M1*CC];

// ---------------------------------------------------------------------------
// PTX helpers
// ---------------------------------------------------------------------------
__device__ __forceinline__ uint32_t smem_u32(const void* p) {
    uint32_t a;
    asm("{ .reg .u64 t; cvta.to.shared.u64 t, %1; cvt.u32.u64 %0, t; }"
        : "=r"(a) : "l"(p));
    return a;
}
__device__ __forceinline__ void cpasync16(uint32_t dst, const void* src) {
    asm volatile("cp.async.cg.shared.global [%0], [%1], 16;"
                 :: "r"(dst), "l"(src) : "memory");
}
#define CP_COMMIT() asm volatile("cp.async.commit_group;" ::: "memory")
#define CP_WAIT(N)  asm volatile("cp.async.wait_group %0;" :: "n"(N) : "memory")

__device__ __forceinline__ void ldsm4(uint32_t& r0, uint32_t& r1, uint32_t& r2,
                                      uint32_t& r3, uint32_t a) {
    asm volatile("ldmatrix.sync.aligned.m8n8.x4.shared.b16 {%0,%1,%2,%3},[%4];"
                 : "=r"(r0), "=r"(r1), "=r"(r2), "=r"(r3) : "r"(a));
}
__device__ __forceinline__ void ldsm4t(uint32_t& r0, uint32_t& r1, uint32_t& r2,
                                       uint32_t& r3, uint32_t a) {
    asm volatile("ldmatrix.sync.aligned.m8n8.x4.trans.shared.b16 {%0,%1,%2,%3},[%4];"
                 : "=r"(r0), "=r"(r1), "=r"(r2), "=r"(r3) : "r"(a));
}
__device__ __forceinline__ void ldsm2t(uint32_t& r0, uint32_t& r1, uint32_t a) {
    asm volatile("ldmatrix.sync.aligned.m8n8.x2.trans.shared.b16 {%0,%1},[%2];"
                 : "=r"(r0), "=r"(r1) : "r"(a));
}
__device__ __forceinline__ void mma16816(float* c, const uint32_t* a,
                                         uint32_t b0, uint32_t b1) {
    asm volatile("mma.sync.aligned.m16n8k16.row.col.f32.f16.f16.f32 "
                 "{%0,%1,%2,%3},{%4,%5,%6,%7},{%8,%9},{%0,%1,%2,%3};"
                 : "+f"(c[0]), "+f"(c[1]), "+f"(c[2]), "+f"(c[3])
                 : "r"(a[0]), "r"(a[1]), "r"(a[2]), "r"(a[3]), "r"(b0), "r"(b1));
}

__device__ __forceinline__ void hi_store(__half* dh, size_t off, float v0, float v1) {
    __half2 hp = __halves2half2(__float2half(v0), __float2half(v1));
    *(uint32_t*)(dh + off) = *(uint32_t*)&hp;
}
__device__ __forceinline__ uint32_t pack_h2(float v0, float v1) {
    __half2 hp = __halves2half2(__float2half(v0), __float2half(v1));
    return *(uint32_t*)&hp;
}
// packed fp16x2 2^x
__device__ __forceinline__ uint32_t h2ex2(uint32_t x) {
    uint32_t r;
    asm volatile("ex2.approx.f16x2 %0, %1;" : "=r"(r) : "r"(x));
    return r;
}

// ---------------------------------------------------------------------------
__global__ __launch_bounds__(256) void convert_x(const float* __restrict__ src)
{
    int i = blockIdx.x * 256 + threadIdx.x;
    float4 v = ((const float4*)src)[i];
    hi_store(g_xh, (size_t)i * 4,     v.x, v.y);
    hi_store(g_xh, (size_t)i * 4 + 2, v.z, v.w);
}

template<int W>
__global__ void transpose_w(const float* __restrict__ w)
{
    __half* th = (W == 0) ? g_wqh : g_wph;
    const int N = (W == 0) ? N_QKV : CC;
    __shared__ float ts[32][33];
    int n0 = blockIdx.x * 32, k0 = blockIdx.y * 32;
    int tx = threadIdx.x, ty = threadIdx.y;
    #pragma unroll
    for (int i = 0; i < 32; i += 8)
        ts[ty + i][tx] = w[(size_t)(k0 + ty + i) * N + n0 + tx];
    __syncthreads();
    #pragma unroll
    for (int i = 0; i < 32; i += 8)
        th[(size_t)(n0 + ty + i) * CC + k0 + tx] = __float2half(ts[tx][ty + i]);
}

// ---------------------------------------------------------------------------
// GEMM: C[128x128] = A[M,1024] @ B^T + bias (R8 config, unchanged).
// ---------------------------------------------------------------------------
#define GST 36864
#define GSMEM (3*GST)

template<int EPI>
__global__ __launch_bounds__(256, 2) void mma_gemm(const float* __restrict__ bias,
                                                   float* __restrict__ outp)
{
    const __half* Ah = (EPI == 0) ? g_xh : g_ah;
    const __half* Bh = (EPI == 0) ? g_wqh : g_wph;

    extern __shared__ char smc[];
    const uint32_t smb = smem_u32(smc);
    const int t = threadIdx.x, wid = t >> 5, l = t & 31;
    const int wm = wid >> 2, wn = wid & 3;
    const int n0 = blockIdx.x * 128, m0 = blockIdx.y * 128;

    float acc[4][4][4];
    #pragma unroll
    for (int i = 0; i < 4; i++)
        #pragma unroll
        for (int j = 0; j < 4; j++)
            #pragma unroll
            for (int k = 0; k < 4; k++) acc[i][j][k] = 0.f;

    auto issue = [&](int s) {
        const int koff = s * 64;
        const uint32_t sb = smb + (s % 3) * GST;
        #pragma unroll
        for (int i = 0; i < 4; i++) {
            int c = t + i * 256;
            int row = c >> 3, q = c & 7;
            uint32_t so = (uint32_t)(row * 144 + q * 16);
            cpasync16(sb + so,         Ah + (size_t)(m0 + row) * CC + koff + q * 8);
            cpasync16(sb + 18432 + so, Bh + (size_t)(n0 + row) * CC + koff + q * 8);
        }
        CP_COMMIT();
    };

    issue(0);
    issue(1);
    for (int s = 0; s < 16; s++) {
        if (s < 14) CP_WAIT(1);
        else        CP_WAIT(0);
        __syncthreads();
        if (s + 2 < 16) issue(s + 2);
        const uint32_t sb = smb + (s % 3) * GST;
        #pragma unroll
        for (int ks = 0; ks < 4; ks++) {
            uint32_t ah[4][4];
            #pragma unroll
            for (int mt = 0; mt < 4; mt++) {
                uint32_t ad = sb + (uint32_t)((wm * 64 + mt * 16 + (l & 15)) * 144
                                              + ks * 32 + (l >> 4) * 16);
                ldsm4(ah[mt][0], ah[mt][1], ah[mt][2], ah[mt][3], ad);
            }
            uint32_t bh[4][2];
            #pragma unroll
            for (int j = 0; j < 2; j++) {
                uint32_t bd = sb + 18432
                    + (uint32_t)((wn * 32 + 16 * j + (l & 7) + ((l >> 4) & 1) * 8) * 144
                                 + ks * 32 + ((l >> 3) & 1) * 16);
                uint32_t r0, r1, r2, r3;
                ldsm4(r0, r1, r2, r3, bd);
                bh[2*j][0] = r0; bh[2*j][1] = r1; bh[2*j+1][0] = r2; bh[2*j+1][1] = r3;
            }
            #pragma unroll
            for (int mt = 0; mt < 4; mt++)
                #pragma unroll
                for (int nt = 0; nt < 4; nt++)
                    mma16816(acc[mt][nt], ah[mt], bh[nt][0], bh[nt][1]);
        }
    }

    #pragma unroll
    for (int mt = 0; mt < 4; mt++) {
        const int rA = m0 + wm * 64 + mt * 16 + (l >> 2);
        const int rB = rA + 8;
        #pragma unroll
        for (int nt = 0; nt < 4; nt++) {
            const int n = n0 + wn * 32 + nt * 8 + 2 * (l & 3);
            const float bi0 = bias[n], bi1 = bias[n + 1];
            float v0 = acc[mt][nt][0] + bi0, v1 = acc[mt][nt][1] + bi1;
            float v2 = acc[mt][nt][2] + bi0, v3 = acc[mt][nt][3] + bi1;
            if (EPI == 0) {
                const int which = n >> 10;
                const int h = (n & 1023) >> 6, d = n & 63;
                const int bA = rA >> 11, tA = rA & 2047;
                const int bB = rB >> 11, tB = rB & 2047;
                const size_t oA = (((size_t)(bA * NH + h)) * TT + tA) * HD + d;
                const size_t oB = (((size_t)(bB * NH + h)) * TT + tB) * HD + d;
                if (which == 0) {
                    hi_store(g_qh, oA, v0 * QSCALE, v1 * QSCALE);
                    hi_store(g_qh, oB, v2 * QSCALE, v3 * QSCALE);
                } else if (which == 1) {
                    hi_store(g_kh, oA, v0, v1);
                    hi_store(g_kh, oB, v2, v3);
                } else {
                    hi_store(g_vh, oA, v0, v1);
                    hi_store(g_vh, oB, v2, v3);
                }
            } else {
                *(float2*)&outp[(size_t)rA * CC + n] = make_float2(v0, v1);
                *(float2*)&outp[(size_t)rB * CC + n] = make_float2(v2, v3);
            }
        }
    }
}

// ---------------------------------------------------------------------------
// Flash attention, fp16, base-2 softmax with f16x2 ex2, l via ones-column mma.
// 256 thr / 8 warps, 128-row q tile, 64-col KV, 3 stages, one sync per tile.
// smem: Qh@0 (18432) | 3 KV stages @18432 + stg*18432 (Kh, Vh@+9216)
// V rows are 144B; bytes 128..143 hold {1.0h, 0...} -> ones column at d=64.
// ---------------------------------------------------------------------------
#define FKV_OFF 18432
#define FKV_ST 18432
#define FLASH_SMEM (FKV_OFF + 3*FKV_ST)   // 73728

__global__ __launch_bounds__(256, 2) void flash_mma()
{
    extern __shared__ char smc[];
    const uint32_t smb = smem_u32(smc);
    const int t = threadIdx.x, w = t >> 5, l = t & 31;
    const int qt = (int)gridDim.x - 1 - (int)blockIdx.x;   // heavy tiles first
    const int h = blockIdx.y, b = blockIdx.z;
    const size_t hoff = ((size_t)(b * NH + h)) * TT * HD;
    const int q0 = qt * 128;
    const int nk = 2 * qt + 2;

    auto kvload = [&](int kt) {
        const uint32_t sb = smb + FKV_OFF + (kt % 3) * FKV_ST;
        const int k0 = kt * 64;
        #pragma unroll
        for (int i = 0; i < 2; i++) {
            int c = t + i * 256, row = c >> 3, q = c & 7;
            uint32_t so = (uint32_t)(row * 144 + q * 16);
            size_t g = hoff + (size_t)(k0 + row) * HD + q * 8;
            cpasync16(sb + so,        g_kh + g);
            cpasync16(sb + 9216 + so, g_vh + g);
        }
        CP_COMMIT();
    };

    // Ones-column init: V padding bytes [128,144) of every row, all 3 stages.
    // kvload never touches these bytes, so this persists for the whole kernel.
    if (t < 192) {
        int stg = t >> 6, row = t & 63;
        *(uint4*)(smc + FKV_OFF + stg * FKV_ST + 9216 + row * 144 + 128) =
            make_uint4(0x00003C00u, 0u, 0u, 0u);   // {1.0h, 0h, 0h*6}
    }

    // Q: 128 rows x 8 chunks = 1024; 256 thr x 4
    #pragma unroll
    for (int i = 0; i < 4; i++) {
        int c = t + i * 256, row = c >> 3, q = c & 7;
        uint32_t so = (uint32_t)(row * 144 + q * 16);
        cpasync16(smb + so, g_qh + hoff + (size_t)(q0 + row) * HD + q * 8);
    }
    kvload(0);
    kvload(1);

    float mA = -1e30f, mB = -1e30f;
    float o[8][4];
    #pragma unroll
    for (int j = 0; j < 8; j++)
        #pragma unroll
        for (int k = 0; k < 4; k++) o[j][k] = 0.f;
    float o_l[4] = {0.f, 0.f, 0.f, 0.f};   // running row-sum fragment (l)

    uint32_t qh[4][4];

    for (int kt = 0; kt < nk; kt++) {
        if (kt < nk - 1) CP_WAIT(1);
        else             CP_WAIT(0);
        __syncthreads();
        if (kt + 2 < nk) kvload(kt + 2);
        if (kt == 0) {
            #pragma unroll
            for (int ks = 0; ks < 4; ks++) {
                uint32_t ad = smb + (uint32_t)((w * 16 + (l & 15)) * 144
                                               + ks * 32 + (l >> 4) * 16);
                ldsm4(qh[ks][0], qh[ks][1], qh[ks][2], qh[ks][3], ad);
            }
        }
        const uint32_t sb = smb + FKV_OFF + (kt % 3) * FKV_ST;

        // S = Q K^T  (S in log2 domain: Q pre-scaled by 1/8*log2e)
        float s[8][4];
        #pragma unroll
        for (int j = 0; j < 8; j++)
            #pragma unroll
            for (int k = 0; k < 4; k++) s[j][k] = 0.f;
        #pragma unroll
        for (int ks = 0; ks < 4; ks++) {
            #pragma unroll
            for (int j = 0; j < 4; j++) {
                uint32_t kd = sb + (uint32_t)((16 * j + (l & 7) + ((l >> 4) & 1) * 8) * 144
                                              + ks * 32 + ((l >> 3) & 1) * 16);
                uint32_t r0, r1, r2, r3;
                ldsm4(r0, r1, r2, r3, kd);
                mma16816(s[2*j],   qh[ks], r0, r1);
                mma16816(s[2*j+1], qh[ks], r2, r3);
            }
        }

        const int rA = q0 + w * 16 + (l >> 2), rB = rA + 8;
        if (kt >= 2 * qt) {
            const int cb = 2 * (l & 3);
            #pragma unroll
            for (int j = 0; j < 8; j++) {
                int cg = kt * 64 + 8 * j + cb;
                if (cg     > rA) s[j][0] = -1e30f;
                if (cg + 1 > rA) s[j][1] = -1e30f;
                if (cg     > rB) s[j][2] = -1e30f;
                if (cg + 1 > rB) s[j][3] = -1e30f;
            }
        }

        // online softmax (base-2): max, rescale, packed fp16 2^x
        float mxA = -1e30f, mxB = -1e30f;
        #pragma unroll
        for (int j = 0; j < 8; j++) {
            mxA = fmaxf(mxA, fmaxf(s[j][0], s[j][1]));
            mxB = fmaxf(mxB, fmaxf(s[j][2], s[j][3]));
        }
        mxA = fmaxf(mxA, __shfl_xor_sync(0xffffffffu, mxA, 1));
        mxA = fmaxf(mxA, __shfl_xor_sync(0xffffffffu, mxA, 2));
        mxB = fmaxf(mxB, __shfl_xor_sync(0xffffffffu, mxB, 1));
        mxB = fmaxf(mxB, __shfl_xor_sync(0xffffffffu, mxB, 2));
        const float nmA = fmaxf(mA, mxA), nmB = fmaxf(mB, mxB);
        const float aA = exp2f(mA - nmA), aB = exp2f(mB - nmB);
        mA = nmA; mB = nmB;

        uint32_t ph[8][2];
        #pragma unroll
        for (int j = 0; j < 8; j++) {
            ph[j][0] = h2ex2(pack_h2(s[j][0] - nmA, s[j][1] - nmA));
            ph[j][1] = h2ex2(pack_h2(s[j][2] - nmB, s[j][3] - nmB));
        }

        #pragma unroll
        for (int j = 0; j < 8; j++) {
            o[j][0] *= aA; o[j][1] *= aA; o[j][2] *= aB; o[j][3] *= aB;
        }
        o_l[0] *= aA; o_l[1] *= aA; o_l[2] *= aB; o_l[3] *= aB;

        // O += P V ; l += P * ones  (V via ldmatrix.trans; ones col at d=64)
        #pragma unroll
        for (int ks = 0; ks < 4; ks++) {
            uint32_t pa[4];
            pa[0] = ph[2*ks][0];   pa[1] = ph[2*ks][1];
            pa[2] = ph[2*ks+1][0]; pa[3] = ph[2*ks+1][1];
            #pragma unroll
            for (int j = 0; j < 4; j++) {
                uint32_t vd = sb + 9216
                    + (uint32_t)((ks * 16 + (l & 7) + ((l >> 3) & 1) * 8) * 144
                                 + 32 * j + ((l >> 4) & 1) * 16);
                uint32_t r0, r1, r2, r3;
                ldsm4t(r0, r1, r2, r3, vd);
                mma16816(o[2*j],   pa, r0, r1);
                mma16816(o[2*j+1], pa, r2, r3);
            }
            uint32_t v0, v1;
            ldsm2t(v0, v1, sb + 9216
                   + (uint32_t)((ks * 16 + (l & 7) + ((l >> 3) & 1) * 8) * 144 + 128));
            mma16816(o_l, pa, v0, v1);
        }
    }

    // l lives in lane (quad base) of o_l[0] (row A) / o_l[2] (row B)
    const int qb = l & ~3;
    const float lA = __shfl_sync(0xffffffffu, o_l[0], qb);
    const float lB = __shfl_sync(0xffffffffu, o_l[2], qb);
    const float iA = 1.f / lA, iB = 1.f / lB;
    const int rA = q0 + w * 16 + (l >> 2), rB = rA + 8;
    const size_t baseA = ((size_t)(b * TT + rA)) * CC + h * HD;
    const size_t baseB = ((size_t)(b * TT + rB)) * CC + h * HD;
    #pragma unroll
    for (int j = 0; j < 8; j++) {
        const int d = 8 * j + 2 * (l & 3);
        hi_store(g_ah, baseA + d, o[j][0] * iA, o[j][1] * iA);
        hi_store(g_ah, baseB + d, o[j][2] * iB, o[j][3] * iB);
    }
}

// ---------------------------------------------------------------------------
extern "C" void kernel_launch(void* const* d_in, const int* in_sizes, int n_in,
                              void* d_out, int out_size)
{
    const float* x      = (const float*)d_in[0];
    const float* w_attn = (const float*)d_in[1];
    const float* b_attn = (const float*)d_in[2];
    const float* w_proj = (const float*)d_in[3];
    const float* b_proj = (const float*)d_in[4];
    float* out = (float*)d_out;

    cudaFuncSetAttribute(mma_gemm<0>, cudaFuncAttributeMaxDynamicSharedMemorySize, GSMEM);
    cudaFuncSetAttribute(mma_gemm<1>, cudaFuncAttributeMaxDynamicSharedMemorySize, GSMEM);
    cudaFuncSetAttribute(flash_mma, cudaFuncAttributeMaxDynamicSharedMemorySize, FLASH_SMEM);

    convert_x<<<M1 * CC / 1024, 256>>>(x);
    transpose_w<0><<<dim3(N_QKV / 32, CC / 32), dim3(32, 8)>>>(w_attn);
    transpose_w<1><<<dim3(CC / 32, CC / 32), dim3(32, 8)>>>(w_proj);

    mma_gemm<0><<<dim3(N_QKV / 128, M1 / 128), 256, GSMEM>>>(b_attn, nullptr);
    flash_mma<<<dim3(TT / 128, NH, BB), 256, FLASH_SMEM>>>();
    mma_gemm<1><<<dim3(CC / 128, M1 / 128), 256, GSMEM>>>(b_proj, out);
}

// round 10
// speedup vs baseline: 1.4310x; 1.0281x over previous
#include <cuda_runtime.h>
#include <cuda_fp16.h>
#include <cstdint>
#include <math.h>

#define BB 4
#define TT 2048
#define CC 1024
#define NH 16
#define HD 64
#define M1 (BB*TT)          // 8192
#define N_QKV (3*CC)        // 3072

// q pre-scale: 1/sqrt(64) * log2(e)  -> softmax computed base-2
#define QSCALE 0.180336880111120436f

// ---------------------------------------------------------------------------
// Device-global scratch: pure fp16 operands.
// ---------------------------------------------------------------------------
__device__ __half g_xh[M1*CC];
__device__ __half g_wqh[N_QKV*CC];
__device__ __half g_wph[CC*CC];
__device__ __half g_qh[BB*NH*TT*HD];
__device__ __half g_kh[BB*NH*TT*HD];
__device__ __half g_vh[BB*NH*TT*HD];
__device__ __half g_ah[M1*CC];

// ---------------------------------------------------------------------------
// PTX helpers
// ---------------------------------------------------------------------------
__device__ __forceinline__ uint32_t smem_u32(const void* p) {
    uint32_t a;
    asm("{ .reg .u64 t; cvta.to.shared.u64 t, %1; cvt.u32.u64 %0, t; }"
        : "=r"(a) : "l"(p));
    return a;
}
__device__ __forceinline__ void cpasync16(uint32_t dst, const void* src) {
    asm volatile("cp.async.cg.shared.global [%0], [%1], 16;"
                 :: "r"(dst), "l"(src) : "memory");
}
#define CP_COMMIT() asm volatile("cp.async.commit_group;" ::: "memory")
#define CP_WAIT(N)  asm volatile("cp.async.wait_group %0;" :: "n"(N) : "memory")

__device__ __forceinline__ void ldsm4(uint32_t& r0, uint32_t& r1, uint32_t& r2,
                                      uint32_t& r3, uint32_t a) {
    asm volatile("ldmatrix.sync.aligned.m8n8.x4.shared.b16 {%0,%1,%2,%3},[%4];"
                 : "=r"(r0), "=r"(r1), "=r"(r2), "=r"(r3) : "r"(a));
}
__device__ __forceinline__ void ldsm4t(uint32_t& r0, uint32_t& r1, uint32_t& r2,
                                       uint32_t& r3, uint32_t a) {
    asm volatile("ldmatrix.sync.aligned.m8n8.x4.trans.shared.b16 {%0,%1,%2,%3},[%4];"
                 : "=r"(r0), "=r"(r1), "=r"(r2), "=r"(r3) : "r"(a));
}
__device__ __forceinline__ void ldsm2t(uint32_t& r0, uint32_t& r1, uint32_t a) {
    asm volatile("ldmatrix.sync.aligned.m8n8.x2.trans.shared.b16 {%0,%1},[%2];"
                 : "=r"(r0), "=r"(r1) : "r"(a));
}
__device__ __forceinline__ void mma16816(float* c, const uint32_t* a,
                                         uint32_t b0, uint32_t b1) {
    asm volatile("mma.sync.aligned.m16n8k16.row.col.f32.f16.f16.f32 "
                 "{%0,%1,%2,%3},{%4,%5,%6,%7},{%8,%9},{%0,%1,%2,%3};"
                 : "+f"(c[0]), "+f"(c[1]), "+f"(c[2]), "+f"(c[3])
                 : "r"(a[0]), "r"(a[1]), "r"(a[2]), "r"(a[3]), "r"(b0), "r"(b1));
}

__device__ __forceinline__ void hi_store(__half* dh, size_t off, float v0, float v1) {
    __half2 hp = __halves2half2(__float2half(v0), __float2half(v1));
    *(uint32_t*)(dh + off) = *(uint32_t*)&hp;
}
__device__ __forceinline__ uint32_t pack_h2(float v0, float v1) {
    __half2 hp = __halves2half2(__float2half(v0), __float2half(v1));
    return *(uint32_t*)&hp;
}
__device__ __forceinline__ uint32_t h2ex2(uint32_t x) {
    uint32_t r;
    asm volatile("ex2.approx.f16x2 %0, %1;" : "=r"(r) : "r"(x));
    return r;
}

// ---------------------------------------------------------------------------
__global__ __launch_bounds__(256) void convert_x(const float* __restrict__ src)
{
    int i = blockIdx.x * 256 + threadIdx.x;
    float4 v = ((const float4*)src)[i];
    hi_store(g_xh, (size_t)i * 4,     v.x, v.y);
    hi_store(g_xh, (size_t)i * 4 + 2, v.z, v.w);
}

template<int W>
__global__ void transpose_w(const float* __restrict__ w)
{
    __half* th = (W == 0) ? g_wqh : g_wph;
    const int N = (W == 0) ? N_QKV : CC;
    __shared__ float ts[32][33];
    int n0 = blockIdx.x * 32, k0 = blockIdx.y * 32;
    int tx = threadIdx.x, ty = threadIdx.y;
    #pragma unroll
    for (int i = 0; i < 32; i += 8)
        ts[ty + i][tx] = w[(size_t)(k0 + ty + i) * N + n0 + tx];
    __syncthreads();
    #pragma unroll
    for (int i = 0; i < 32; i += 8)
        th[(size_t)(n0 + ty + i) * CC + k0 + tx] = __float2half(ts[tx][ty + i]);
}

// ---------------------------------------------------------------------------
// GEMM (R8/R9 config, unchanged): 256 thr, 8 warps 64x32, BK=64, 3 stages.
// ---------------------------------------------------------------------------
#define GST 36864
#define GSMEM (3*GST)

template<int EPI>
__global__ __launch_bounds__(256, 2) void mma_gemm(const float* __restrict__ bias,
                                                   float* __restrict__ outp)
{
    const __half* Ah = (EPI == 0) ? g_xh : g_ah;
    const __half* Bh = (EPI == 0) ? g_wqh : g_wph;

    extern __shared__ char smc[];
    const uint32_t smb = smem_u32(smc);
    const int t = threadIdx.x, wid = t >> 5, l = t & 31;
    const int wm = wid >> 2, wn = wid & 3;
    const int n0 = blockIdx.x * 128, m0 = blockIdx.y * 128;

    float acc[4][4][4];
    #pragma unroll
    for (int i = 0; i < 4; i++)
        #pragma unroll
        for (int j = 0; j < 4; j++)
            #pragma unroll
            for (int k = 0; k < 4; k++) acc[i][j][k] = 0.f;

    auto issue = [&](int s) {
        const int koff = s * 64;
        const uint32_t sb = smb + (s % 3) * GST;
        #pragma unroll
        for (int i = 0; i < 4; i++) {
            int c = t + i * 256;
            int row = c >> 3, q = c & 7;
            uint32_t so = (uint32_t)(row * 144 + q * 16);
            cpasync16(sb + so,         Ah + (size_t)(m0 + row) * CC + koff + q * 8);
            cpasync16(sb + 18432 + so, Bh + (size_t)(n0 + row) * CC + koff + q * 8);
        }
        CP_COMMIT();
    };

    issue(0);
    issue(1);
    for (int s = 0; s < 16; s++) {
        if (s < 14) CP_WAIT(1);
        else        CP_WAIT(0);
        __syncthreads();
        if (s + 2 < 16) issue(s + 2);
        const uint32_t sb = smb + (s % 3) * GST;
        #pragma unroll
        for (int ks = 0; ks < 4; ks++) {
            uint32_t ah[4][4];
            #pragma unroll
            for (int mt = 0; mt < 4; mt++) {
                uint32_t ad = sb + (uint32_t)((wm * 64 + mt * 16 + (l & 15)) * 144
                                              + ks * 32 + (l >> 4) * 16);
                ldsm4(ah[mt][0], ah[mt][1], ah[mt][2], ah[mt][3], ad);
            }
            uint32_t bh[4][2];
            #pragma unroll
            for (int j = 0; j < 2; j++) {
                uint32_t bd = sb + 18432
                    + (uint32_t)((wn * 32 + 16 * j + (l & 7) + ((l >> 4) & 1) * 8) * 144
                                 + ks * 32 + ((l >> 3) & 1) * 16);
                uint32_t r0, r1, r2, r3;
                ldsm4(r0, r1, r2, r3, bd);
                bh[2*j][0] = r0; bh[2*j][1] = r1; bh[2*j+1][0] = r2; bh[2*j+1][1] = r3;
            }
            #pragma unroll
            for (int mt = 0; mt < 4; mt++)
                #pragma unroll
                for (int nt = 0; nt < 4; nt++)
                    mma16816(acc[mt][nt], ah[mt], bh[nt][0], bh[nt][1]);
        }
    }

    #pragma unroll
    for (int mt = 0; mt < 4; mt++) {
        const int rA = m0 + wm * 64 + mt * 16 + (l >> 2);
        const int rB = rA + 8;
        #pragma unroll
        for (int nt = 0; nt < 4; nt++) {
            const int n = n0 + wn * 32 + nt * 8 + 2 * (l & 3);
            const float bi0 = bias[n], bi1 = bias[n + 1];
            float v0 = acc[mt][nt][0] + bi0, v1 = acc[mt][nt][1] + bi1;
            float v2 = acc[mt][nt][2] + bi0, v3 = acc[mt][nt][3] + bi1;
            if (EPI == 0) {
                const int which = n >> 10;
                const int h = (n & 1023) >> 6, d = n & 63;
                const int bA = rA >> 11, tA = rA & 2047;
                const int bB = rB >> 11, tB = rB & 2047;
                const size_t oA = (((size_t)(bA * NH + h)) * TT + tA) * HD + d;
                const size_t oB = (((size_t)(bB * NH + h)) * TT + tB) * HD + d;
                if (which == 0) {
                    hi_store(g_qh, oA, v0 * QSCALE, v1 * QSCALE);
                    hi_store(g_qh, oB, v2 * QSCALE, v3 * QSCALE);
                } else if (which == 1) {
                    hi_store(g_kh, oA, v0, v1);
                    hi_store(g_kh, oB, v2, v3);
                } else {
                    hi_store(g_vh, oA, v0, v1);
                    hi_store(g_vh, oB, v2, v3);
                }
            } else {
                *(float2*)&outp[(size_t)rA * CC + n] = make_float2(v0, v1);
                *(float2*)&outp[(size_t)rB * CC + n] = make_float2(v2, v3);
            }
        }
    }
}

// ---------------------------------------------------------------------------
// Flash attention, fp16, base-2 f16x2-ex2 softmax, l via ones-column mma.
// NEW: 128 thr / 4 warps; each warp owns 32 q-rows (2 m-frags) ->
// every K/V ldsm fragment feeds 2 MMAs (halved smem read traffic).
// 4 KV stages. smem: Qh@0 (18432) | 4 stages @18432 + stg*18432 (Kh, Vh@+9216)
// V rows 144B; bytes 128..143 hold {1.0h,0...} -> ones column at d=64.
// ---------------------------------------------------------------------------
#define FKV_OFF 18432
#define FKV_ST 18432
#define FLASH_SMEM (FKV_OFF + 4*FKV_ST)   // 92160

__global__ __launch_bounds__(128, 2) void flash_mma()
{
    extern __shared__ char smc[];
    const uint32_t smb = smem_u32(smc);
    const int t = threadIdx.x, w = t >> 5, l = t & 31;
    const int qt = (int)gridDim.x - 1 - (int)blockIdx.x;   // heavy tiles first
    const int h = blockIdx.y, b = blockIdx.z;
    const size_t hoff = ((size_t)(b * NH + h)) * TT * HD;
    const int q0 = qt * 128;
    const int nk = 2 * qt + 2;

    auto kvload = [&](int kt) {
        const uint32_t sb = smb + FKV_OFF + (kt & 3) * FKV_ST;
        const int k0 = kt * 64;
        #pragma unroll
        for (int i = 0; i < 4; i++) {
            int c = t + i * 128, row = c >> 3, q = c & 7;
            uint32_t so = (uint32_t)(row * 144 + q * 16);
            size_t g = hoff + (size_t)(k0 + row) * HD + q * 8;
            cpasync16(sb + so,        g_kh + g);
            cpasync16(sb + 9216 + so, g_vh + g);
        }
        CP_COMMIT();
    };

    // Ones-column init: V padding bytes [128,144) of every row, all 4 stages.
    // kvload never touches these bytes; persists for the whole kernel.
    for (int i = t; i < 256; i += 128) {
        int stg = i >> 6, row = i & 63;
        *(uint4*)(smc + FKV_OFF + stg * FKV_ST + 9216 + row * 144 + 128) =
            make_uint4(0x00003C00u, 0u, 0u, 0u);
    }

    // Q: 128 rows x 8 chunks = 1024; 128 thr x 8 (shares group with kvload(0))
    #pragma unroll
    for (int i = 0; i < 8; i++) {
        int c = t + i * 128, row = c >> 3, q = c & 7;
        uint32_t so = (uint32_t)(row * 144 + q * 16);
        cpasync16(smb + so, g_qh + hoff + (size_t)(q0 + row) * HD + q * 8);
    }
    kvload(0);
    if (1 < nk) kvload(1);
    if (2 < nk) kvload(2);

    float mr[2][2];
    float o[2][8][4];
    float o_l[2][4];
    #pragma unroll
    for (int mt = 0; mt < 2; mt++) {
        mr[mt][0] = -1e30f; mr[mt][1] = -1e30f;
        #pragma unroll
        for (int j = 0; j < 8; j++)
            #pragma unroll
            for (int k = 0; k < 4; k++) o[mt][j][k] = 0.f;
        #pragma unroll
        for (int k = 0; k < 4; k++) o_l[mt][k] = 0.f;
    }

    uint32_t qh[2][4][4];

    for (int kt = 0; kt < nk; kt++) {
        if (kt + 3 < nk) CP_WAIT(2);
        else             CP_WAIT(0);
        __syncthreads();
        if (kt + 3 < nk) kvload(kt + 3);
        if (kt == 0) {
            #pragma unroll
            for (int mt = 0; mt < 2; mt++)
                #pragma unroll
                for (int ks = 0; ks < 4; ks++) {
                    uint32_t ad = smb + (uint32_t)((w * 32 + mt * 16 + (l & 15)) * 144
                                                   + ks * 32 + (l >> 4) * 16);
                    ldsm4(qh[mt][ks][0], qh[mt][ks][1], qh[mt][ks][2], qh[mt][ks][3], ad);
                }
        }
        const uint32_t sb = smb + FKV_OFF + (kt & 3) * FKV_ST;

        // S = Q K^T  (each K fragment feeds both m-frags)
        float s[2][8][4];
        #pragma unroll
        for (int mt = 0; mt < 2; mt++)
            #pragma unroll
            for (int j = 0; j < 8; j++)
                #pragma unroll
                for (int k = 0; k < 4; k++) s[mt][j][k] = 0.f;
        #pragma unroll
        for (int ks = 0; ks < 4; ks++) {
            #pragma unroll
            for (int j = 0; j < 4; j++) {
                uint32_t kd = sb + (uint32_t)((16 * j + (l & 7) + ((l >> 4) & 1) * 8) * 144
                                              + ks * 32 + ((l >> 3) & 1) * 16);
                uint32_t r0, r1, r2, r3;
                ldsm4(r0, r1, r2, r3, kd);
                #pragma unroll
                for (int mt = 0; mt < 2; mt++) {
                    mma16816(s[mt][2*j],   qh[mt][ks], r0, r1);
                    mma16816(s[mt][2*j+1], qh[mt][ks], r2, r3);
                }
            }
        }

        if (kt >= 2 * qt) {
            const int cb = 2 * (l & 3);
            #pragma unroll
            for (int mt = 0; mt < 2; mt++) {
                const int rA = q0 + w * 32 + mt * 16 + (l >> 2), rB = rA + 8;
                #pragma unroll
                for (int j = 0; j < 8; j++) {
                    int cg = kt * 64 + 8 * j + cb;
                    if (cg     > rA) s[mt][j][0] = -1e30f;
                    if (cg + 1 > rA) s[mt][j][1] = -1e30f;
                    if (cg     > rB) s[mt][j][2] = -1e30f;
                    if (cg + 1 > rB) s[mt][j][3] = -1e30f;
                }
            }
        }

        // online softmax (base-2, per m-frag), pack P to fp16
        uint32_t ph[2][8][2];
        #pragma unroll
        for (int mt = 0; mt < 2; mt++) {
            float mxA = -1e30f, mxB = -1e30f;
            #pragma unroll
            for (int j = 0; j < 8; j++) {
                mxA = fmaxf(mxA, fmaxf(s[mt][j][0], s[mt][j][1]));
                mxB = fmaxf(mxB, fmaxf(s[mt][j][2], s[mt][j][3]));
            }
            mxA = fmaxf(mxA, __shfl_xor_sync(0xffffffffu, mxA, 1));
            mxA = fmaxf(mxA, __shfl_xor_sync(0xffffffffu, mxA, 2));
            mxB = fmaxf(mxB, __shfl_xor_sync(0xffffffffu, mxB, 1));
            mxB = fmaxf(mxB, __shfl_xor_sync(0xffffffffu, mxB, 2));
            const float nmA = fmaxf(mr[mt][0], mxA), nmB = fmaxf(mr[mt][1], mxB);
            const float aA = exp2f(mr[mt][0] - nmA), aB = exp2f(mr[mt][1] - nmB);
            mr[mt][0] = nmA; mr[mt][1] = nmB;
            #pragma unroll
            for (int j = 0; j < 8; j++) {
                ph[mt][j][0] = h2ex2(pack_h2(s[mt][j][0] - nmA, s[mt][j][1] - nmA));
                ph[mt][j][1] = h2ex2(pack_h2(s[mt][j][2] - nmB, s[mt][j][3] - nmB));
            }
            #pragma unroll
            for (int j = 0; j < 8; j++) {
                o[mt][j][0] *= aA; o[mt][j][1] *= aA;
                o[mt][j][2] *= aB; o[mt][j][3] *= aB;
            }
            o_l[mt][0] *= aA; o_l[mt][1] *= aA;
            o_l[mt][2] *= aB; o_l[mt][3] *= aB;
        }

        // O += P V ; l += P * ones  (each V fragment feeds both m-frags)
        #pragma unroll
        for (int ks = 0; ks < 4; ks++) {
            uint32_t pa[2][4];
            #pragma unroll
            for (int mt = 0; mt < 2; mt++) {
                pa[mt][0] = ph[mt][2*ks][0];   pa[mt][1] = ph[mt][2*ks][1];
                pa[mt][2] = ph[mt][2*ks+1][0]; pa[mt][3] = ph[mt][2*ks+1][1];
            }
            #pragma unroll
            for (int j = 0; j < 4; j++) {
                uint32_t vd = sb + 9216
                    + (uint32_t)((ks * 16 + (l & 7) + ((l >> 3) & 1) * 8) * 144
                                 + 32 * j + ((l >> 4) & 1) * 16);
                uint32_t r0, r1, r2, r3;
                ldsm4t(r0, r1, r2, r3, vd);
                #pragma unroll
                for (int mt = 0; mt < 2; mt++) {
                    mma16816(o[mt][2*j],   pa[mt], r0, r1);
                    mma16816(o[mt][2*j+1], pa[mt], r2, r3);
                }
            }
            uint32_t v0, v1;
            ldsm2t(v0, v1, sb + 9216
                   + (uint32_t)((ks * 16 + (l & 7) + ((l >> 3) & 1) * 8) * 144 + 128));
            #pragma unroll
            for (int mt = 0; mt < 2; mt++)
                mma16816(o_l[mt], pa[mt], v0, v1);
        }
    }

    // l lives at quad-base lane of o_l[mt][0] (row A) / o_l[mt][2] (row B)
    const int qb = l & ~3;
    #pragma unroll
    for (int mt = 0; mt < 2; mt++) {
        const float lA = __shfl_sync(0xffffffffu, o_l[mt][0], qb);
        const float lB = __shfl_sync(0xffffffffu, o_l[mt][2], qb);
        const float iA = 1.f / lA, iB = 1.f / lB;
        const int rA = q0 + w * 32 + mt * 16 + (l >> 2), rB = rA + 8;
        const size_t baseA = ((size_t)(b * TT + rA)) * CC + h * HD;
        const size_t baseB = ((size_t)(b * TT + rB)) * CC + h * HD;
        #pragma unroll
        for (int j = 0; j < 8; j++) {
            const int d = 8 * j + 2 * (l & 3);
            hi_store(g_ah, baseA + d, o[mt][j][0] * iA, o[mt][j][1] * iA);
            hi_store(g_ah, baseB + d, o[mt][j][2] * iB, o[mt][j][3] * iB);
        }
    }
}

// ---------------------------------------------------------------------------
extern "C" void kernel_launch(void* const* d_in, const int* in_sizes, int n_in,
                              void* d_out, int out_size)
{
    const float* x      = (const float*)d_in[0];
    const float* w_attn = (const float*)d_in[1];
    const float* b_attn = (const float*)d_in[2];
    const float* w_proj = (const float*)d_in[3];
    const float* b_proj = (const float*)d_in[4];
    float* out = (float*)d_out;

    cudaFuncSetAttribute(mma_gemm<0>, cudaFuncAttributeMaxDynamicSharedMemorySize, GSMEM);
    cudaFuncSetAttribute(mma_gemm<1>, cudaFuncAttributeMaxDynamicSharedMemorySize, GSMEM);
    cudaFuncSetAttribute(flash_mma, cudaFuncAttributeMaxDynamicSharedMemorySize, FLASH_SMEM);

    convert_x<<<M1 * CC / 1024, 256>>>(x);
    transpose_w<0><<<dim3(N_QKV / 32, CC / 32), dim3(32, 8)>>>(w_attn);
    transpose_w<1><<<dim3(CC / 32, CC / 32), dim3(32, 8)>>>(w_proj);

    mma_gemm<0><<<dim3(N_QKV / 128, M1 / 128), 256, GSMEM>>>(b_attn, nullptr);
    flash_mma<<<dim3(TT / 128, NH, BB), 128, FLASH_SMEM>>>();
    mma_gemm<1><<<dim3(CC / 128, M1 / 128), 256, GSMEM>>>(b_proj, out);
}

// round 11
// speedup vs baseline: 1.4728x; 1.0292x over previous
#include <cuda_runtime.h>
#include <cuda_fp16.h>
#include <cstdint>
#include <math.h>

#define BB 4
#define TT 2048
#define CC 1024
#define NH 16
#define HD 64
#define M1 (BB*TT)          // 8192
#define N_QKV (3*CC)        // 3072

// q pre-scale: 1/sqrt(64) * log2(e)  -> softmax computed base-2
#define QSCALE 0.180336880111120436f

// ---------------------------------------------------------------------------
// Device-global scratch: pure fp16 operands.  Weights kept K-major [K,N].
// ---------------------------------------------------------------------------
__device__ __half g_xh[M1*CC];
__device__ __half g_wq[CC*N_QKV];     // [K=1024, N=3072] fp16
__device__ __half g_wp[CC*CC];        // [K=1024, N=1024] fp16
__device__ __half g_qh[BB*NH*TT*HD];
__device__ __half g_kh[BB*NH*TT*HD];
__device__ __half g_vh[BB*NH*TT*HD];
__device__ __half g_ah[M1*CC];

// ---------------------------------------------------------------------------
// PTX helpers
// ---------------------------------------------------------------------------
__device__ __forceinline__ uint32_t smem_u32(const void* p) {
    uint32_t a;
    asm("{ .reg .u64 t; cvta.to.shared.u64 t, %1; cvt.u32.u64 %0, t; }"
        : "=r"(a) : "l"(p));
    return a;
}
__device__ __forceinline__ void cpasync16(uint32_t dst, const void* src) {
    asm volatile("cp.async.cg.shared.global [%0], [%1], 16;"
                 :: "r"(dst), "l"(src) : "memory");
}
#define CP_COMMIT() asm volatile("cp.async.commit_group;" ::: "memory")
#define CP_WAIT(N)  asm volatile("cp.async.wait_group %0;" :: "n"(N) : "memory")

__device__ __forceinline__ void ldsm4(uint32_t& r0, uint32_t& r1, uint32_t& r2,
                                      uint32_t& r3, uint32_t a) {
    asm volatile("ldmatrix.sync.aligned.m8n8.x4.shared.b16 {%0,%1,%2,%3},[%4];"
                 : "=r"(r0), "=r"(r1), "=r"(r2), "=r"(r3) : "r"(a));
}
__device__ __forceinline__ void ldsm4t(uint32_t& r0, uint32_t& r1, uint32_t& r2,
                                       uint32_t& r3, uint32_t a) {
    asm volatile("ldmatrix.sync.aligned.m8n8.x4.trans.shared.b16 {%0,%1,%2,%3},[%4];"
                 : "=r"(r0), "=r"(r1), "=r"(r2), "=r"(r3) : "r"(a));
}
__device__ __forceinline__ void ldsm2t(uint32_t& r0, uint32_t& r1, uint32_t a) {
    asm volatile("ldmatrix.sync.aligned.m8n8.x2.trans.shared.b16 {%0,%1},[%2];"
                 : "=r"(r0), "=r"(r1) : "r"(a));
}
__device__ __forceinline__ void mma16816(float* c, const uint32_t* a,
                                         uint32_t b0, uint32_t b1) {
    asm volatile("mma.sync.aligned.m16n8k16.row.col.f32.f16.f16.f32 "
                 "{%0,%1,%2,%3},{%4,%5,%6,%7},{%8,%9},{%0,%1,%2,%3};"
                 : "+f"(c[0]), "+f"(c[1]), "+f"(c[2]), "+f"(c[3])
                 : "r"(a[0]), "r"(a[1]), "r"(a[2]), "r"(a[3]), "r"(b0), "r"(b1));
}

__device__ __forceinline__ void hi_store(__half* dh, size_t off, float v0, float v1) {
    __half2 hp = __halves2half2(__float2half(v0), __float2half(v1));
    *(uint32_t*)(dh + off) = *(uint32_t*)&hp;
}
__device__ __forceinline__ uint32_t pack_h2(float v0, float v1) {
    __half2 hp = __halves2half2(__float2half(v0), __float2half(v1));
    return *(uint32_t*)&hp;
}
__device__ __forceinline__ uint32_t h2ex2(uint32_t x) {
    uint32_t r;
    asm volatile("ex2.approx.f16x2 %0, %1;" : "=r"(r) : "r"(x));
    return r;
}

// ---------------------------------------------------------------------------
// Fused prep: x, w_attn, w_proj fp32 -> fp16 (coalesced, no transpose)
// ---------------------------------------------------------------------------
#define N_X4  (M1*CC/4)          // 2097152
#define N_WQ4 (CC*N_QKV/4)       // 786432
#define N_WP4 (CC*CC/4)          // 262144
#define PREP_BLOCKS ((N_X4 + N_WQ4 + N_WP4) / 256)   // 12288

__global__ __launch_bounds__(256) void prep_convert(const float* __restrict__ x,
                                                    const float* __restrict__ wa,
                                                    const float* __restrict__ wp)
{
    int i = blockIdx.x * 256 + threadIdx.x;
    const float* src;
    __half* dst;
    if (i < N_X4)               { src = x;  dst = g_xh; }
    else if (i < N_X4 + N_WQ4)  { i -= N_X4;  src = wa; dst = g_wq; }
    else                        { i -= N_X4 + N_WQ4; src = wp; dst = g_wp; }
    float4 v = ((const float4*)src)[i];
    hi_store(dst, (size_t)i * 4,     v.x, v.y);
    hi_store(dst, (size_t)i * 4 + 2, v.z, v.w);
}

// ---------------------------------------------------------------------------
// GEMM: C[128x128] = A[M,1024] @ W[1024,N] tile + bias. fp16, fp32 accum.
// 256 thr, 8 warps (2x4) 64x32 tiles, BK=64, 3 stages.
// A smem: 128 rows x 144B (K-frag via ldsm4).
// B smem: 64 k-rows x 272B (256B = 128 n-halfs + 16B pad; n-frag via ldsm4t).
// ---------------------------------------------------------------------------
#define GSTA 18432
#define GSTB 17408
#define GST  (GSTA + GSTB)       // 35840
#define GSMEM (3*GST)            // 107520

template<int EPI>
__global__ __launch_bounds__(256, 2) void mma_gemm(const float* __restrict__ bias,
                                                   float* __restrict__ outp)
{
    const __half* Ah = (EPI == 0) ? g_xh : g_ah;
    const __half* Bw = (EPI == 0) ? g_wq : g_wp;
    const int N = (EPI == 0) ? N_QKV : CC;

    extern __shared__ char smc[];
    const uint32_t smb = smem_u32(smc);
    const int t = threadIdx.x, wid = t >> 5, l = t & 31;
    const int wm = wid >> 2, wn = wid & 3;
    const int n0 = blockIdx.x * 128, m0 = blockIdx.y * 128;

    float acc[4][4][4];
    #pragma unroll
    for (int i = 0; i < 4; i++)
        #pragma unroll
        for (int j = 0; j < 4; j++)
            #pragma unroll
            for (int k = 0; k < 4; k++) acc[i][j][k] = 0.f;

    auto issue = [&](int s) {
        const int koff = s * 64;
        const uint32_t sb = smb + (s % 3) * GST;
        // A: 128 rows x 8 chunks = 1024
        #pragma unroll
        for (int i = 0; i < 4; i++) {
            int c = t + i * 256;
            int row = c >> 3, q = c & 7;
            cpasync16(sb + (uint32_t)(row * 144 + q * 16),
                      Ah + (size_t)(m0 + row) * CC + koff + q * 8);
        }
        // B: 64 k-rows x 16 chunks = 1024
        #pragma unroll
        for (int i = 0; i < 4; i++) {
            int c = t + i * 256;
            int row = c >> 4, q = c & 15;
            cpasync16(sb + GSTA + (uint32_t)(row * 272 + q * 16),
                      Bw + (size_t)(koff + row) * N + n0 + q * 8);
        }
        CP_COMMIT();
    };

    issue(0);
    issue(1);
    for (int s = 0; s < 16; s++) {
        if (s < 14) CP_WAIT(1);
        else        CP_WAIT(0);
        __syncthreads();
        if (s + 2 < 16) issue(s + 2);
        const uint32_t sb = smb + (s % 3) * GST;
        #pragma unroll
        for (int ks = 0; ks < 4; ks++) {
            uint32_t ah[4][4];
            #pragma unroll
            for (int mt = 0; mt < 4; mt++) {
                uint32_t ad = sb + (uint32_t)((wm * 64 + mt * 16 + (l & 15)) * 144
                                              + ks * 32 + (l >> 4) * 16);
                ldsm4(ah[mt][0], ah[mt][1], ah[mt][2], ah[mt][3], ad);
            }
            uint32_t bh[4][2];
            #pragma unroll
            for (int jj = 0; jj < 2; jj++) {
                uint32_t bd = sb + GSTA
                    + (uint32_t)((ks * 16 + (l & 7) + ((l >> 3) & 1) * 8) * 272
                                 + wn * 64 + jj * 32 + ((l >> 4) & 1) * 16);
                uint32_t r0, r1, r2, r3;
                ldsm4t(r0, r1, r2, r3, bd);
                bh[2*jj][0] = r0; bh[2*jj][1] = r1;
                bh[2*jj+1][0] = r2; bh[2*jj+1][1] = r3;
            }
            #pragma unroll
            for (int mt = 0; mt < 4; mt++)
                #pragma unroll
                for (int nt = 0; nt < 4; nt++)
                    mma16816(acc[mt][nt], ah[mt], bh[nt][0], bh[nt][1]);
        }
    }

    #pragma unroll
    for (int mt = 0; mt < 4; mt++) {
        const int rA = m0 + wm * 64 + mt * 16 + (l >> 2);
        const int rB = rA + 8;
        #pragma unroll
        for (int nt = 0; nt < 4; nt++) {
            const int n = n0 + wn * 32 + nt * 8 + 2 * (l & 3);
            const float bi0 = bias[n], bi1 = bias[n + 1];
            float v0 = acc[mt][nt][0] + bi0, v1 = acc[mt][nt][1] + bi1;
            float v2 = acc[mt][nt][2] + bi0, v3 = acc[mt][nt][3] + bi1;
            if (EPI == 0) {
                const int which = n >> 10;
                const int h = (n & 1023) >> 6, d = n & 63;
                const int bA = rA >> 11, tA = rA & 2047;
                const int bB = rB >> 11, tB = rB & 2047;
                const size_t oA = (((size_t)(bA * NH + h)) * TT + tA) * HD + d;
                const size_t oB = (((size_t)(bB * NH + h)) * TT + tB) * HD + d;
                if (which == 0) {
                    hi_store(g_qh, oA, v0 * QSCALE, v1 * QSCALE);
                    hi_store(g_qh, oB, v2 * QSCALE, v3 * QSCALE);
                } else if (which == 1) {
                    hi_store(g_kh, oA, v0, v1);
                    hi_store(g_kh, oB, v2, v3);
                } else {
                    hi_store(g_vh, oA, v0, v1);
                    hi_store(g_vh, oB, v2, v3);
                }
            } else {
                *(float2*)&outp[(size_t)rA * CC + n] = make_float2(v0, v1);
                *(float2*)&outp[(size_t)rB * CC + n] = make_float2(v2, v3);
            }
        }
    }
}

// ---------------------------------------------------------------------------
// Flash attention (R10 config, unchanged): 128 thr / 4 warps, 2 m-frags/warp,
// 128-row q tile, 64-col KV, 4 stages, base-2 f16x2-ex2 softmax,
// l via ones-column mma (V padding bytes hold {1.0h,0...}).
// ---------------------------------------------------------------------------
#define FKV_OFF 18432
#define FKV_ST 18432
#define FLASH_SMEM (FKV_OFF + 4*FKV_ST)   // 92160

__global__ __launch_bounds__(128, 2) void flash_mma()
{
    extern __shared__ char smc[];
    const uint32_t smb = smem_u32(smc);
    const int t = threadIdx.x, w = t >> 5, l = t & 31;
    const int qt = (int)gridDim.x - 1 - (int)blockIdx.x;
    const int h = blockIdx.y, b = blockIdx.z;
    const size_t hoff = ((size_t)(b * NH + h)) * TT * HD;
    const int q0 = qt * 128;
    const int nk = 2 * qt + 2;

    auto kvload = [&](int kt) {
        const uint32_t sb = smb + FKV_OFF + (kt & 3) * FKV_ST;
        const int k0 = kt * 64;
        #pragma unroll
        for (int i = 0; i < 4; i++) {
            int c = t + i * 128, row = c >> 3, q = c & 7;
            uint32_t so = (uint32_t)(row * 144 + q * 16);
            size_t g = hoff + (size_t)(k0 + row) * HD + q * 8;
            cpasync16(sb + so,        g_kh + g);
            cpasync16(sb + 9216 + so, g_vh + g);
        }
        CP_COMMIT();
    };

    for (int i = t; i < 256; i += 128) {
        int stg = i >> 6, row = i & 63;
        *(uint4*)(smc + FKV_OFF + stg * FKV_ST + 9216 + row * 144 + 128) =
            make_uint4(0x00003C00u, 0u, 0u, 0u);
    }

    #pragma unroll
    for (int i = 0; i < 8; i++) {
        int c = t + i * 128, row = c >> 3, q = c & 7;
        uint32_t so = (uint32_t)(row * 144 + q * 16);
        cpasync16(smb + so, g_qh + hoff + (size_t)(q0 + row) * HD + q * 8);
    }
    kvload(0);
    if (1 < nk) kvload(1);
    if (2 < nk) kvload(2);

    float mr[2][2];
    float o[2][8][4];
    float o_l[2][4];
    #pragma unroll
    for (int mt = 0; mt < 2; mt++) {
        mr[mt][0] = -1e30f; mr[mt][1] = -1e30f;
        #pragma unroll
        for (int j = 0; j < 8; j++)
            #pragma unroll
            for (int k = 0; k < 4; k++) o[mt][j][k] = 0.f;
        #pragma unroll
        for (int k = 0; k < 4; k++) o_l[mt][k] = 0.f;
    }

    uint32_t qh[2][4][4];

    for (int kt = 0; kt < nk; kt++) {
        if (kt + 3 < nk) CP_WAIT(2);
        else             CP_WAIT(0);
        __syncthreads();
        if (kt + 3 < nk) kvload(kt + 3);
        if (kt == 0) {
            #pragma unroll
            for (int mt = 0; mt < 2; mt++)
                #pragma unroll
                for (int ks = 0; ks < 4; ks++) {
                    uint32_t ad = smb + (uint32_t)((w * 32 + mt * 16 + (l & 15)) * 144
                                                   + ks * 32 + (l >> 4) * 16);
                    ldsm4(qh[mt][ks][0], qh[mt][ks][1], qh[mt][ks][2], qh[mt][ks][3], ad);
                }
        }
        const uint32_t sb = smb + FKV_OFF + (kt & 3) * FKV_ST;

        float s[2][8][4];
        #pragma unroll
        for (int mt = 0; mt < 2; mt++)
            #pragma unroll
            for (int j = 0; j < 8; j++)
                #pragma unroll
                for (int k = 0; k < 4; k++) s[mt][j][k] = 0.f;
        #pragma unroll
        for (int ks = 0; ks < 4; ks++) {
            #pragma unroll
            for (int j = 0; j < 4; j++) {
                uint32_t kd = sb + (uint32_t)((16 * j + (l & 7) + ((l >> 4) & 1) * 8) * 144
                                              + ks * 32 + ((l >> 3) & 1) * 16);
                uint32_t r0, r1, r2, r3;
                ldsm4(r0, r1, r2, r3, kd);
                #pragma unroll
                for (int mt = 0; mt < 2; mt++) {
                    mma16816(s[mt][2*j],   qh[mt][ks], r0, r1);
                    mma16816(s[mt][2*j+1], qh[mt][ks], r2, r3);
                }
            }
        }

        if (kt >= 2 * qt) {
            const int cb = 2 * (l & 3);
            #pragma unroll
            for (int mt = 0; mt < 2; mt++) {
                const int rA = q0 + w * 32 + mt * 16 + (l >> 2), rB = rA + 8;
                #pragma unroll
                for (int j = 0; j < 8; j++) {
                    int cg = kt * 64 + 8 * j + cb;
                    if (cg     > rA) s[mt][j][0] = -1e30f;
                    if (cg + 1 > rA) s[mt][j][1] = -1e30f;
                    if (cg     > rB) s[mt][j][2] = -1e30f;
                    if (cg + 1 > rB) s[mt][j][3] = -1e30f;
                }
            }
        }

        uint32_t ph[2][8][2];
        #pragma unroll
        for (int mt = 0; mt < 2; mt++) {
            float mxA = -1e30f, mxB = -1e30f;
            #pragma unroll
            for (int j = 0; j < 8; j++) {
                mxA = fmaxf(mxA, fmaxf(s[mt][j][0], s[mt][j][1]));
                mxB = fmaxf(mxB, fmaxf(s[mt][j][2], s[mt][j][3]));
            }
            mxA = fmaxf(mxA, __shfl_xor_sync(0xffffffffu, mxA, 1));
            mxA = fmaxf(mxA, __shfl_xor_sync(0xffffffffu, mxA, 2));
            mxB = fmaxf(mxB, __shfl_xor_sync(0xffffffffu, mxB, 1));
            mxB = fmaxf(mxB, __shfl_xor_sync(0xffffffffu, mxB, 2));
            const float nmA = fmaxf(mr[mt][0], mxA), nmB = fmaxf(mr[mt][1], mxB);
            const float aA = exp2f(mr[mt][0] - nmA), aB = exp2f(mr[mt][1] - nmB);
            mr[mt][0] = nmA; mr[mt][1] = nmB;
            #pragma unroll
            for (int j = 0; j < 8; j++) {
                ph[mt][j][0] = h2ex2(pack_h2(s[mt][j][0] - nmA, s[mt][j][1] - nmA));
                ph[mt][j][1] = h2ex2(pack_h2(s[mt][j][2] - nmB, s[mt][j][3] - nmB));
            }
            #pragma unroll
            for (int j = 0; j < 8; j++) {
                o[mt][j][0] *= aA; o[mt][j][1] *= aA;
                o[mt][j][2] *= aB; o[mt][j][3] *= aB;
            }
            o_l[mt][0] *= aA; o_l[mt][1] *= aA;
            o_l[mt][2] *= aB; o_l[mt][3] *= aB;
        }

        #pragma unroll
        for (int ks = 0; ks < 4; ks++) {
            uint32_t pa[2][4];
            #pragma unroll
            for (int mt = 0; mt < 2; mt++) {
                pa[mt][0] = ph[mt][2*ks][0];   pa[mt][1] = ph[mt][2*ks][1];
                pa[mt][2] = ph[mt][2*ks+1][0]; pa[mt][3] = ph[mt][2*ks+1][1];
            }
            #pragma unroll
            for (int j = 0; j < 4; j++) {
                uint32_t vd = sb + 9216
                    + (uint32_t)((ks * 16 + (l & 7) + ((l >> 3) & 1) * 8) * 144
                                 + 32 * j + ((l >> 4) & 1) * 16);
                uint32_t r0, r1, r2, r3;
                ldsm4t(r0, r1, r2, r3, vd);
                #pragma unroll
                for (int mt = 0; mt < 2; mt++) {
                    mma16816(o[mt][2*j],   pa[mt], r0, r1);
                    mma16816(o[mt][2*j+1], pa[mt], r2, r3);
                }
            }
            uint32_t v0, v1;
            ldsm2t(v0, v1, sb + 9216
                   + (uint32_t)((ks * 16 + (l & 7) + ((l >> 3) & 1) * 8) * 144 + 128));
            #pragma unroll
            for (int mt = 0; mt < 2; mt++)
                mma16816(o_l[mt], pa[mt], v0, v1);
        }
    }

    const int qb = l & ~3;
    #pragma unroll
    for (int mt = 0; mt < 2; mt++) {
        const float lA = __shfl_sync(0xffffffffu, o_l[mt][0], qb);
        const float lB = __shfl_sync(0xffffffffu, o_l[mt][2], qb);
        const float iA = 1.f / lA, iB = 1.f / lB;
        const int rA = q0 + w * 32 + mt * 16 + (l >> 2), rB = rA + 8;
        const size_t baseA = ((size_t)(b * TT + rA)) * CC + h * HD;
        const size_t baseB = ((size_t)(b * TT + rB)) * CC + h * HD;
        #pragma unroll
        for (int j = 0; j < 8; j++) {
            const int d = 8 * j + 2 * (l & 3);
            hi_store(g_ah, baseA + d, o[mt][j][0] * iA, o[mt][j][1] * iA);
            hi_store(g_ah, baseB + d, o[mt][j][2] * iB, o[mt][j][3] * iB);
        }
    }
}

// ---------------------------------------------------------------------------
extern "C" void kernel_launch(void* const* d_in, const int* in_sizes, int n_in,
                              void* d_out, int out_size)
{
    const float* x      = (const float*)d_in[0];
    const float* w_attn = (const float*)d_in[1];
    const float* b_attn = (const float*)d_in[2];
    const float* w_proj = (const float*)d_in[3];
    const float* b_proj = (const float*)d_in[4];
    float* out = (float*)d_out;

    cudaFuncSetAttribute(mma_gemm<0>, cudaFuncAttributeMaxDynamicSharedMemorySize, GSMEM);
    cudaFuncSetAttribute(mma_gemm<1>, cudaFuncAttributeMaxDynamicSharedMemorySize, GSMEM);
    cudaFuncSetAttribute(flash_mma, cudaFuncAttributeMaxDynamicSharedMemorySize, FLASH_SMEM);

    prep_convert<<<PREP_BLOCKS, 256>>>(x, w_attn, w_proj);
    mma_gemm<0><<<dim3(N_QKV / 128, M1 / 128), 256, GSMEM>>>(b_attn, nullptr);
    flash_mma<<<dim3(TT / 128, NH, BB), 128, FLASH_SMEM>>>();
    mma_gemm<1><<<dim3(CC / 128, M1 / 128), 256, GSMEM>>>(b_proj, out);
}